// round 8
// baseline (speedup 1.0000x reference)
#include <cuda_runtime.h>
#include <cuda_bf16.h>
#include <cstdint>
#include <math.h>

#define B_   2
#define S_   2048
#define H_   16
#define DH_  64
#define DM_  1024
#define MTOK (B_ * S_)        // 4096

// ---------------- scratch (device-code references ONLY) ----------------
__device__ float g_qkv[(size_t)MTOK * 3 * DM_];     // 48 MB
__device__ float g_ao [(size_t)MTOK * DM_];         // 16 MB

// bf16 hi/lo GEMM operands
__device__ __nv_bfloat16 g_xh [(size_t)MTOK * DM_];
__device__ __nv_bfloat16 g_xl [(size_t)MTOK * DM_];
__device__ __nv_bfloat16 g_wqh[(size_t)3 * DM_ * DM_];
__device__ __nv_bfloat16 g_wql[(size_t)3 * DM_ * DM_];
__device__ __nv_bfloat16 g_woh[(size_t)DM_ * DM_];
__device__ __nv_bfloat16 g_wol[(size_t)DM_ * DM_];
__device__ __nv_bfloat16 g_aoh[(size_t)MTOK * DM_];
__device__ __nv_bfloat16 g_aol[(size_t)MTOK * DM_];

// bf16 hi/lo attention operands (Q has 0.125 score scale folded in)
__device__ __nv_bfloat16 g_qhi[(size_t)B_ * H_ * S_ * DH_];
__device__ __nv_bfloat16 g_qlo[(size_t)B_ * H_ * S_ * DH_];
__device__ __nv_bfloat16 g_khi[(size_t)B_ * H_ * S_ * DH_];
__device__ __nv_bfloat16 g_klo[(size_t)B_ * H_ * S_ * DH_];
__device__ __nv_bfloat16 g_vthi[(size_t)B_ * H_ * DH_ * S_];  // transposed [bh][d][s]
__device__ __nv_bfloat16 g_vtlo[(size_t)B_ * H_ * DH_ * S_];

// ---------------- helpers ----------------
__device__ __forceinline__ uint32_t smem_u32(const void* p) {
    uint32_t a;
    asm("{ .reg .u64 t; cvta.to.shared.u64 t, %1; cvt.u32.u64 %0, t; }"
        : "=r"(a) : "l"(p));
    return a;
}

__device__ __forceinline__ void cp16(uint32_t dst, const void* src) {
    asm volatile("cp.async.cg.shared.global [%0], [%1], 16;"
                 :: "r"(dst), "l"(src));
}
#define CP_COMMIT() asm volatile("cp.async.commit_group;" ::: "memory")
#define CP_WAIT(n)  asm volatile("cp.async.wait_group %0;" :: "n"(n) : "memory")

__device__ __forceinline__ void mma16816(float* d, const uint32_t* a,
                                         uint32_t b0, uint32_t b1) {
    asm volatile(
        "mma.sync.aligned.m16n8k16.row.col.f32.bf16.bf16.f32 "
        "{%0,%1,%2,%3}, {%4,%5,%6,%7}, {%8,%9}, {%0,%1,%2,%3};"
        : "+f"(d[0]), "+f"(d[1]), "+f"(d[2]), "+f"(d[3])
        : "r"(a[0]), "r"(a[1]), "r"(a[2]), "r"(a[3]), "r"(b0), "r"(b1));
}

__device__ __forceinline__ uint32_t pack_bf16(float x, float y) {
    __nv_bfloat162 t(__float2bfloat16(x), __float2bfloat16(y));
    return *(uint32_t*)&t;
}

// ---------------- fp32 -> bf16 hi/lo split (one-time, streaming) ----------
__global__ void __launch_bounds__(256) k_splitg(const float* __restrict__ in,
                                                int which)
{
    __nv_bfloat16 *hi, *lo;
    if      (which == 0) { hi = g_xh;  lo = g_xl;  }
    else if (which == 1) { hi = g_wqh; lo = g_wql; }
    else if (which == 2) { hi = g_woh; lo = g_wol; }
    else                 { hi = g_aoh; lo = g_aol; in = g_ao; }

    int i = (blockIdx.x * 256 + threadIdx.x) * 4;
    float4 v = *(const float4*)(in + i);
    __nv_bfloat16 h0 = __float2bfloat16(v.x);
    __nv_bfloat16 h1 = __float2bfloat16(v.y);
    __nv_bfloat16 h2 = __float2bfloat16(v.z);
    __nv_bfloat16 h3 = __float2bfloat16(v.w);
    *(__nv_bfloat162*)(hi + i)     = __nv_bfloat162(h0, h1);
    *(__nv_bfloat162*)(hi + i + 2) = __nv_bfloat162(h2, h3);
    *(__nv_bfloat162*)(lo + i)     = __nv_bfloat162(
        __float2bfloat16(v.x - __bfloat162float(h0)),
        __float2bfloat16(v.y - __bfloat162float(h1)));
    *(__nv_bfloat162*)(lo + i + 2) = __nv_bfloat162(
        __float2bfloat16(v.z - __bfloat162float(h2)),
        __float2bfloat16(v.w - __bfloat162float(h3)));
}

// ---------------- HMMA split-bf16 GEMM, cp.async double-buffered -----------
// C[M,N] = Ahi.Bhi^T + Ahi.Blo^T + Alo.Bhi^T ; operands [.,1024] K-major bf16.
// CTA tile 128x128, BK=32, 256 threads = 8 warps (4x2), warp tile 32x64.
#define LDAH  40                 // smem row stride in halves (64B data + 16B pad)
#define TILEH (128 * LDAH)       // halves per tile (5120)
#define GEMM_SMEM (8 * TILEH * 2)   // 2 bufs x 4 tiles = 81920 B

__device__ __forceinline__ void gemm_pre(const __nv_bfloat16* __restrict__ Ahi,
                                         const __nv_bfloat16* __restrict__ Alo,
                                         const __nv_bfloat16* __restrict__ Bhi,
                                         const __nv_bfloat16* __restrict__ Blo,
                                         float* __restrict__ C, int N)
{
    extern __shared__ __align__(16) __nv_bfloat16 sm[];
    const uint32_t sbase = smem_u32(sm);

    const int tid  = threadIdx.x;
    const int lane = tid & 31;
    const int wid  = tid >> 5;
    const int wm   = wid & 3;
    const int wn   = wid >> 2;
    const int gid  = lane >> 2;
    const int tig  = lane & 3;
    const int bm   = blockIdx.y * 128;
    const int bn   = blockIdx.x * 128;

    const int row0 = tid >> 1;             // 0..127
    const int sg0  = (tid & 1) * 2;        // 16B segs {0,1} or {2,3}

    auto issue = [&](int c, int buf) {
        const int kk = c << 5;             // K offset in halves
        const uint32_t b0 = sbase + (uint32_t)buf * 4 * TILEH * 2;
        const uint32_t roff = (uint32_t)(row0 * LDAH) * 2;
#pragma unroll
        for (int i = 0; i < 2; i++) {
            const uint32_t so = roff + (sg0 + i) * 16;
            const int ke = kk + (sg0 + i) * 8;
            cp16(b0 + 0 * TILEH * 2 + so, Ahi + (size_t)(bm + row0) * DM_ + ke);
            cp16(b0 + 1 * TILEH * 2 + so, Alo + (size_t)(bm + row0) * DM_ + ke);
            cp16(b0 + 2 * TILEH * 2 + so, Bhi + (size_t)(bn + row0) * DM_ + ke);
            cp16(b0 + 3 * TILEH * 2 + so, Blo + (size_t)(bn + row0) * DM_ + ke);
        }
        CP_COMMIT();
    };

    float acc[2][8][4];
#pragma unroll
    for (int i = 0; i < 2; i++)
#pragma unroll
        for (int j = 0; j < 8; j++)
#pragma unroll
            for (int k = 0; k < 4; k++) acc[i][j][k] = 0.0f;

    issue(0, 0);

    const int NC = DM_ / 32;               // 32 chunks
    for (int c = 0; c < NC; c++) {
        __syncthreads();                   // all warps done reading buf[(c+1)&1]
        if (c + 1 < NC) { issue(c + 1, (c + 1) & 1); CP_WAIT(1); }
        else            { CP_WAIT(0); }
        __syncthreads();                   // deposits visible to all threads

        const __nv_bfloat16* Ah = sm + (size_t)(c & 1) * 4 * TILEH;
        const __nv_bfloat16* Al = Ah + TILEH;
        const __nv_bfloat16* Bh = Ah + 2 * TILEH;
        const __nv_bfloat16* Bl = Ah + 3 * TILEH;

#pragma unroll
        for (int ks = 0; ks < 2; ks++) {
            const int kb = ks * 16 + tig * 2;

            uint32_t ah[2][4], al[2][4];
#pragma unroll
            for (int mi = 0; mi < 2; mi++) {
                const int r = wm * 32 + mi * 16 + gid;
                ah[mi][0] = *(const uint32_t*)&Ah[r * LDAH + kb];
                ah[mi][1] = *(const uint32_t*)&Ah[(r + 8) * LDAH + kb];
                ah[mi][2] = *(const uint32_t*)&Ah[r * LDAH + kb + 8];
                ah[mi][3] = *(const uint32_t*)&Ah[(r + 8) * LDAH + kb + 8];
                al[mi][0] = *(const uint32_t*)&Al[r * LDAH + kb];
                al[mi][1] = *(const uint32_t*)&Al[(r + 8) * LDAH + kb];
                al[mi][2] = *(const uint32_t*)&Al[r * LDAH + kb + 8];
                al[mi][3] = *(const uint32_t*)&Al[(r + 8) * LDAH + kb + 8];
            }
#pragma unroll
            for (int ng = 0; ng < 8; ng++) {
                const int rn = wn * 64 + ng * 8 + gid;
                uint32_t bh0 = *(const uint32_t*)&Bh[rn * LDAH + kb];
                uint32_t bh1 = *(const uint32_t*)&Bh[rn * LDAH + kb + 8];
                uint32_t bl0 = *(const uint32_t*)&Bl[rn * LDAH + kb];
                uint32_t bl1 = *(const uint32_t*)&Bl[rn * LDAH + kb + 8];
                mma16816(acc[0][ng], ah[0], bh0, bh1);
                mma16816(acc[1][ng], ah[1], bh0, bh1);
                mma16816(acc[0][ng], ah[0], bl0, bl1);
                mma16816(acc[1][ng], ah[1], bl0, bl1);
                mma16816(acc[0][ng], al[0], bh0, bh1);
                mma16816(acc[1][ng], al[1], bh0, bh1);
            }
        }
    }

#pragma unroll
    for (int mi = 0; mi < 2; mi++) {
        const int r = bm + wm * 32 + mi * 16 + gid;
#pragma unroll
        for (int ng = 0; ng < 8; ng++) {
            const int col = bn + wn * 64 + ng * 8 + tig * 2;
            *(float2*)&C[(size_t)r * N + col] =
                make_float2(acc[mi][ng][0], acc[mi][ng][1]);
            *(float2*)&C[(size_t)(r + 8) * N + col] =
                make_float2(acc[mi][ng][2], acc[mi][ng][3]);
        }
    }
}

__global__ void __launch_bounds__(256) k_gemm_qkv()
{
    gemm_pre(g_xh, g_xl, g_wqh, g_wql, g_qkv, 3 * DM_);
}

__global__ void __launch_bounds__(256) k_gemm_out(float* __restrict__ out)
{
    gemm_pre(g_aoh, g_aol, g_woh, g_wol, out, DM_);
}

// ---------------- RoPE + bf16 hi/lo split + head layout + V transpose ------
__global__ void __launch_bounds__(256) k_rope(const int* __restrict__ tp)
{
    int idx = blockIdx.x * 256 + threadIdx.x;
    int i = idx & 31;
    int s = (idx >> 5) & (S_ - 1);
    int h = (idx >> 16) & (H_ - 1);
    int b = idx >> 20;

    const int m = b * S_ + s;
    const float* base = g_qkv + (size_t)m * (3 * DM_) + h * DH_;

    float pos = (float)tp[s];
    float inv = powf(10000.0f, -(float)i * (1.0f / 32.0f));
    float ang = pos * inv;
    float sn, cs;
    sincosf(ang, &sn, &cs);

    float qe = base[2 * i],            qo = base[2 * i + 1];
    float ke = base[DM_ + 2 * i],      ko = base[DM_ + 2 * i + 1];
    float ve = base[2 * DM_ + 2 * i],  vo = base[2 * DM_ + 2 * i + 1];

    float rqe = (qe * cs - qo * sn) * 0.125f;
    float rqo = (qo * cs + qe * sn) * 0.125f;
    float rke = ke * cs - ko * sn;
    float rko = ko * cs + ke * sn;

    size_t o = ((size_t)(b * H_ + h) * S_ + s) * DH_ + 2 * i;

    __nv_bfloat16 qh0 = __float2bfloat16(rqe), qh1 = __float2bfloat16(rqo);
    __nv_bfloat16 kh0 = __float2bfloat16(rke), kh1 = __float2bfloat16(rko);
    *(__nv_bfloat162*)&g_qhi[o] = __nv_bfloat162(qh0, qh1);
    *(__nv_bfloat162*)&g_qlo[o] = __nv_bfloat162(
        __float2bfloat16(rqe - __bfloat162float(qh0)),
        __float2bfloat16(rqo - __bfloat162float(qh1)));
    *(__nv_bfloat162*)&g_khi[o] = __nv_bfloat162(kh0, kh1);
    *(__nv_bfloat162*)&g_klo[o] = __nv_bfloat162(
        __float2bfloat16(rke - __bfloat162float(kh0)),
        __float2bfloat16(rko - __bfloat162float(kh1)));

    // V transpose via smem: block = one (b,h), 8 consecutive s
    __shared__ __nv_bfloat16 svh[64][10], svl[64][10];
    const int sl = (threadIdx.x >> 5) & 7;
    __nv_bfloat16 vh0 = __float2bfloat16(ve), vh1 = __float2bfloat16(vo);
    svh[2 * i][sl]     = vh0;
    svh[2 * i + 1][sl] = vh1;
    svl[2 * i][sl]     = __float2bfloat16(ve - __bfloat162float(vh0));
    svl[2 * i + 1][sl] = __float2bfloat16(vo - __bfloat162float(vh1));
    __syncthreads();

    if (threadIdx.x < 128) {
        const int s0  = (blockIdx.x * 8) & (S_ - 1);
        const int idx0 = blockIdx.x * 256;
        const int h0  = (idx0 >> 16) & (H_ - 1);
        const int b0  = idx0 >> 20;
        const int bh  = b0 * H_ + h0;
        const int d   = threadIdx.x >> 1;
        const int sg  = (threadIdx.x & 1) * 4;

        unsigned short uh[4], ul[4];
#pragma unroll
        for (int j = 0; j < 4; j++) {
            uh[j] = *(unsigned short*)&svh[d][sg + j];
            ul[j] = *(unsigned short*)&svl[d][sg + j];
        }
        size_t vo_ = ((size_t)bh * DH_ + d) * S_ + s0 + sg;
        *(uint2*)&g_vthi[vo_] = *(uint2*)uh;
        *(uint2*)&g_vtlo[vo_] = *(uint2*)ul;
    }
}

// ---------------- HMMA flash attention, cp.async double-buffered -----------
// grid (S/64, B*H), 128 threads = 4 warps; warp = 16 q-rows, key tiles of 64.
#define LDK 72
#define ATILEH (64 * LDK)               // halves per tile (4608)
#define ATTN_SMEM (8 * ATILEH * 2)      // 2 bufs x 4 tiles = 73728 B

__global__ void __launch_bounds__(128) k_attn_mma()
{
    extern __shared__ __align__(16) __nv_bfloat16 sma[];
    const uint32_t sbase = smem_u32(sma);

    const int bh  = blockIdx.y;
    const int q0  = blockIdx.x * 64;
    const int tid = threadIdx.x;
    const int lane = tid & 31;
    const int w    = tid >> 5;
    const int gid  = lane >> 2;
    const int tig  = lane & 3;

    const __nv_bfloat16* qhi = g_qhi + (size_t)bh * S_ * DH_;
    const __nv_bfloat16* qlo = g_qlo + (size_t)bh * S_ * DH_;
    const __nv_bfloat16* khi = g_khi + (size_t)bh * S_ * DH_;
    const __nv_bfloat16* klo = g_klo + (size_t)bh * S_ * DH_;
    const __nv_bfloat16* vth = g_vthi + (size_t)bh * DH_ * S_;
    const __nv_bfloat16* vtl = g_vtlo + (size_t)bh * DH_ * S_;

    const int row0 = tid >> 1;            // 0..63
    const int sg0  = (tid & 1) * 4;       // 16B segs {0..3} or {4..7}

    // ---- stage Q tile into buf0 Khi/Klo regions, extract fragments ----
#pragma unroll
    for (int i2 = 0; i2 < 4; i2++) {
        const int sg = (sg0 + i2) * 8;
        *(uint4*)&sma[row0 * LDK + sg] =
            *(const uint4*)(qhi + (size_t)(q0 + row0) * DH_ + sg);
        *(uint4*)&sma[ATILEH + row0 * LDK + sg] =
            *(const uint4*)(qlo + (size_t)(q0 + row0) * DH_ + sg);
    }
    __syncthreads();

    uint32_t qh[4][4], ql[4][4];
    const int r = w * 16 + gid;
#pragma unroll
    for (int kb = 0; kb < 4; kb++) {
        const int kbase = kb * 16 + tig * 2;
        qh[kb][0] = *(const uint32_t*)&sma[r * LDK + kbase];
        qh[kb][1] = *(const uint32_t*)&sma[(r + 8) * LDK + kbase];
        qh[kb][2] = *(const uint32_t*)&sma[r * LDK + kbase + 8];
        qh[kb][3] = *(const uint32_t*)&sma[(r + 8) * LDK + kbase + 8];
        ql[kb][0] = *(const uint32_t*)&sma[ATILEH + r * LDK + kbase];
        ql[kb][1] = *(const uint32_t*)&sma[ATILEH + (r + 8) * LDK + kbase];
        ql[kb][2] = *(const uint32_t*)&sma[ATILEH + r * LDK + kbase + 8];
        ql[kb][3] = *(const uint32_t*)&sma[ATILEH + (r + 8) * LDK + kbase + 8];
    }
    __syncthreads();

    auto issue = [&](int kt, int buf) {
        const uint32_t b0 = sbase + (uint32_t)buf * 4 * ATILEH * 2;
        const uint32_t roff = (uint32_t)(row0 * LDK) * 2;
#pragma unroll
        for (int i2 = 0; i2 < 4; i2++) {
            const int sg = (sg0 + i2) * 8;
            const uint32_t so = roff + sg * 2;
            cp16(b0 + 0 * ATILEH * 2 + so, khi + (size_t)(kt + row0) * DH_ + sg);
            cp16(b0 + 1 * ATILEH * 2 + so, klo + (size_t)(kt + row0) * DH_ + sg);
            cp16(b0 + 2 * ATILEH * 2 + so, vth + (size_t)row0 * S_ + kt + sg);
            cp16(b0 + 3 * ATILEH * 2 + so, vtl + (size_t)row0 * S_ + kt + sg);
        }
        CP_COMMIT();
    };

    float o[8][4];
#pragma unroll
    for (int j = 0; j < 8; j++)
#pragma unroll
        for (int c = 0; c < 4; c++) o[j][c] = 0.0f;
    float m0 = -INFINITY, m1 = -INFINITY, l0 = 0.0f, l1 = 0.0f;

    const int r0a = q0 + w * 16 + gid;

    const int NT = q0 / 64 + 1;
    issue(0, 0);

    for (int t = 0; t < NT; t++) {
        __syncthreads();                  // all warps done reading buf[(t+1)&1]
        if (t + 1 < NT) { issue((t + 1) * 64, (t + 1) & 1); CP_WAIT(1); }
        else            { CP_WAIT(0); }
        __syncthreads();

        const __nv_bfloat16* Kh = sma + (size_t)(t & 1) * 4 * ATILEH;
        const __nv_bfloat16* Kl = Kh + ATILEH;
        const __nv_bfloat16* Vh = Kh + 2 * ATILEH;
        const __nv_bfloat16* Vl = Kh + 3 * ATILEH;
        const int kt = t * 64;

        // ---- scores ----
        float s[8][4];
#pragma unroll
        for (int j = 0; j < 8; j++)
#pragma unroll
            for (int c = 0; c < 4; c++) s[j][c] = 0.0f;

#pragma unroll
        for (int kb = 0; kb < 4; kb++) {
            const int kbase = kb * 16 + tig * 2;
#pragma unroll
            for (int j = 0; j < 8; j++) {
                const int rn = j * 8 + gid;
                uint32_t kh0 = *(const uint32_t*)&Kh[rn * LDK + kbase];
                uint32_t kh1 = *(const uint32_t*)&Kh[rn * LDK + kbase + 8];
                uint32_t kl0 = *(const uint32_t*)&Kl[rn * LDK + kbase];
                uint32_t kl1 = *(const uint32_t*)&Kl[rn * LDK + kbase + 8];
                mma16816(s[j], qh[kb], kh0, kh1);
                mma16816(s[j], qh[kb], kl0, kl1);
                mma16816(s[j], ql[kb], kh0, kh1);
            }
        }

        // ---- causal mask (diagonal block only) ----
        if (t == NT - 1) {
#pragma unroll
            for (int j = 0; j < 8; j++) {
                const int cb = kt + j * 8 + 2 * tig;
                if (cb     > r0a)     s[j][0] = -INFINITY;
                if (cb + 1 > r0a)     s[j][1] = -INFINITY;
                if (cb     > r0a + 8) s[j][2] = -INFINITY;
                if (cb + 1 > r0a + 8) s[j][3] = -INFINITY;
            }
        }

        // ---- online softmax ----
        float tm0 = m0, tm1 = m1;
#pragma unroll
        for (int j = 0; j < 8; j++) {
            tm0 = fmaxf(tm0, fmaxf(s[j][0], s[j][1]));
            tm1 = fmaxf(tm1, fmaxf(s[j][2], s[j][3]));
        }
        tm0 = fmaxf(tm0, __shfl_xor_sync(0xffffffff, tm0, 1));
        tm0 = fmaxf(tm0, __shfl_xor_sync(0xffffffff, tm0, 2));
        tm1 = fmaxf(tm1, __shfl_xor_sync(0xffffffff, tm1, 1));
        tm1 = fmaxf(tm1, __shfl_xor_sync(0xffffffff, tm1, 2));

        const float sc0 = __expf(m0 - tm0);
        const float sc1 = __expf(m1 - tm1);
        m0 = tm0; m1 = tm1;
        l0 *= sc0; l1 *= sc1;
#pragma unroll
        for (int j = 0; j < 8; j++) {
            o[j][0] *= sc0; o[j][1] *= sc0;
            o[j][2] *= sc1; o[j][3] *= sc1;
        }

        float rs0 = 0.0f, rs1 = 0.0f;
#pragma unroll
        for (int j = 0; j < 8; j++) {
            s[j][0] = __expf(s[j][0] - m0);
            s[j][1] = __expf(s[j][1] - m0);
            s[j][2] = __expf(s[j][2] - m1);
            s[j][3] = __expf(s[j][3] - m1);
            rs0 += s[j][0] + s[j][1];
            rs1 += s[j][2] + s[j][3];
        }
        rs0 += __shfl_xor_sync(0xffffffff, rs0, 1);
        rs0 += __shfl_xor_sync(0xffffffff, rs0, 2);
        rs1 += __shfl_xor_sync(0xffffffff, rs1, 1);
        rs1 += __shfl_xor_sync(0xffffffff, rs1, 2);
        l0 += rs0; l1 += rs1;

        // ---- P into A-fragments (hi/lo) ----
        uint32_t ph[4][4], pl[4][4];
#pragma unroll
        for (int kb = 0; kb < 4; kb++) {
            const int j0 = 2 * kb, j1 = 2 * kb + 1;
            ph[kb][0] = pack_bf16(s[j0][0], s[j0][1]);
            ph[kb][1] = pack_bf16(s[j0][2], s[j0][3]);
            ph[kb][2] = pack_bf16(s[j1][0], s[j1][1]);
            ph[kb][3] = pack_bf16(s[j1][2], s[j1][3]);
            __nv_bfloat162 h0 = *(__nv_bfloat162*)&ph[kb][0];
            __nv_bfloat162 h1 = *(__nv_bfloat162*)&ph[kb][1];
            __nv_bfloat162 h2 = *(__nv_bfloat162*)&ph[kb][2];
            __nv_bfloat162 h3 = *(__nv_bfloat162*)&ph[kb][3];
            pl[kb][0] = pack_bf16(s[j0][0] - __bfloat162float(h0.x),
                                  s[j0][1] - __bfloat162float(h0.y));
            pl[kb][1] = pack_bf16(s[j0][2] - __bfloat162float(h1.x),
                                  s[j0][3] - __bfloat162float(h1.y));
            pl[kb][2] = pack_bf16(s[j1][0] - __bfloat162float(h2.x),
                                  s[j1][1] - __bfloat162float(h2.y));
            pl[kb][3] = pack_bf16(s[j1][2] - __bfloat162float(h3.x),
                                  s[j1][3] - __bfloat162float(h3.y));
        }

        // ---- O += P.V ----
#pragma unroll
        for (int kb = 0; kb < 4; kb++) {
            const int kbase = kb * 16 + tig * 2;
#pragma unroll
            for (int j = 0; j < 8; j++) {
                const int rn = j * 8 + gid;
                uint32_t vh0 = *(const uint32_t*)&Vh[rn * LDK + kbase];
                uint32_t vh1 = *(const uint32_t*)&Vh[rn * LDK + kbase + 8];
                uint32_t vl0 = *(const uint32_t*)&Vl[rn * LDK + kbase];
                uint32_t vl1 = *(const uint32_t*)&Vl[rn * LDK + kbase + 8];
                mma16816(o[j], ph[kb], vh0, vh1);
                mma16816(o[j], ph[kb], vl0, vl1);
                mma16816(o[j], pl[kb], vh0, vh1);
            }
        }
    }

    // ---- epilogue ----
    const float inv0 = 1.0f / l0;
    const float inv1 = 1.0f / l1;
    const int b = bh >> 4, h = bh & 15;
#pragma unroll
    for (int j = 0; j < 8; j++) {
        const int col = h * DH_ + j * 8 + 2 * tig;
        *(float2*)&g_ao[(size_t)(b * S_ + r0a) * DM_ + col] =
            make_float2(o[j][0] * inv0, o[j][1] * inv0);
        *(float2*)&g_ao[(size_t)(b * S_ + r0a + 8) * DM_ + col] =
            make_float2(o[j][2] * inv1, o[j][3] * inv1);
    }
}

// ---------------- launch ----------------
extern "C" void kernel_launch(void* const* d_in, const int* in_sizes, int n_in,
                              void* d_out, int out_size)
{
    const float* x      = (const float*)d_in[0];
    const float* w_qkv  = (const float*)d_in[1];
    const float* w_o    = (const float*)d_in[2];
    const int*   tp     = (const int*)d_in[3];

    static bool attr_done = false;
    if (!attr_done) {
        cudaFuncSetAttribute(k_gemm_qkv,
            cudaFuncAttributeMaxDynamicSharedMemorySize, GEMM_SMEM);
        cudaFuncSetAttribute(k_gemm_out,
            cudaFuncAttributeMaxDynamicSharedMemorySize, GEMM_SMEM);
        cudaFuncSetAttribute(k_attn_mma,
            cudaFuncAttributeMaxDynamicSharedMemorySize, ATTN_SMEM);
        attr_done = true;
    }

    // 0) one-time bf16 hi/lo splits of x, w_qkv, w_o
    k_splitg<<<(MTOK * DM_) / 1024, 256>>>(x, 0);
    k_splitg<<<(3 * DM_ * DM_) / 1024, 256>>>(w_qkv, 1);
    k_splitg<<<(DM_ * DM_) / 1024, 256>>>(w_o, 2);

    // 1) QKV projection (HMMA + cp.async)
    k_gemm_qkv<<<dim3(3 * DM_ / 128, MTOK / 128), 256, GEMM_SMEM>>>();

    // 2) RoPE + bf16 hi/lo per-head layout + V transpose
    k_rope<<<(B_ * H_ * S_ * 32) / 256, 256>>>(tp);

    // 3) causal flash attention (HMMA + cp.async)
    k_attn_mma<<<dim3(S_ / 64, B_ * H_), 128, ATTN_SMEM>>>();

    // 4) split attention output, output projection (HMMA + cp.async)
    k_splitg<<<(MTOK * DM_) / 1024, 256>>>(nullptr, 3);
    k_gemm_out<<<dim3(DM_ / 128, MTOK / 128), 256, GEMM_SMEM>>>((float*)d_out);
}

// round 9
// speedup vs baseline: 1.3968x; 1.3968x over previous
#include <cuda_runtime.h>
#include <cuda_bf16.h>
#include <cstdint>
#include <math.h>

#define B_   2
#define S_   2048
#define H_   16
#define DH_  64
#define DM_  1024
#define MTOK (B_ * S_)        // 4096

// ---------------- scratch (device-code references ONLY) ----------------
__device__ float g_qkv[(size_t)MTOK * 3 * DM_];     // 48 MB
__device__ float g_ao [(size_t)MTOK * DM_];         // 16 MB

// bf16 hi/lo GEMM operands
__device__ __nv_bfloat16 g_xh [(size_t)MTOK * DM_];
__device__ __nv_bfloat16 g_xl [(size_t)MTOK * DM_];
__device__ __nv_bfloat16 g_wqh[(size_t)3 * DM_ * DM_];
__device__ __nv_bfloat16 g_wql[(size_t)3 * DM_ * DM_];
__device__ __nv_bfloat16 g_woh[(size_t)DM_ * DM_];
__device__ __nv_bfloat16 g_wol[(size_t)DM_ * DM_];
__device__ __nv_bfloat16 g_aoh[(size_t)MTOK * DM_];
__device__ __nv_bfloat16 g_aol[(size_t)MTOK * DM_];

// bf16 hi/lo attention operands (Q has 0.125 score scale folded in)
__device__ __nv_bfloat16 g_qhi[(size_t)B_ * H_ * S_ * DH_];
__device__ __nv_bfloat16 g_qlo[(size_t)B_ * H_ * S_ * DH_];
__device__ __nv_bfloat16 g_khi[(size_t)B_ * H_ * S_ * DH_];
__device__ __nv_bfloat16 g_klo[(size_t)B_ * H_ * S_ * DH_];
__device__ __nv_bfloat16 g_vthi[(size_t)B_ * H_ * DH_ * S_];  // transposed [bh][d][s]
__device__ __nv_bfloat16 g_vtlo[(size_t)B_ * H_ * DH_ * S_];

// ---------------- helpers ----------------
__device__ __forceinline__ void mma16816(float* d, const uint32_t* a,
                                         uint32_t b0, uint32_t b1) {
    asm volatile(
        "mma.sync.aligned.m16n8k16.row.col.f32.bf16.bf16.f32 "
        "{%0,%1,%2,%3}, {%4,%5,%6,%7}, {%8,%9}, {%0,%1,%2,%3};"
        : "+f"(d[0]), "+f"(d[1]), "+f"(d[2]), "+f"(d[3])
        : "r"(a[0]), "r"(a[1]), "r"(a[2]), "r"(a[3]), "r"(b0), "r"(b1));
}

__device__ __forceinline__ uint32_t pack_bf16(float x, float y) {
    __nv_bfloat162 t(__float2bfloat16(x), __float2bfloat16(y));
    return *(uint32_t*)&t;
}

// ---------------- fp32 -> bf16 hi/lo split (one-time, streaming) ----------
__global__ void __launch_bounds__(256) k_splitg(const float* __restrict__ in,
                                                int which)
{
    __nv_bfloat16 *hi, *lo;
    if      (which == 0) { hi = g_xh;  lo = g_xl;  }
    else if (which == 1) { hi = g_wqh; lo = g_wql; }
    else if (which == 2) { hi = g_woh; lo = g_wol; }
    else                 { hi = g_aoh; lo = g_aol; in = g_ao; }

    int i = (blockIdx.x * 256 + threadIdx.x) * 4;
    float4 v = *(const float4*)(in + i);
    __nv_bfloat16 h0 = __float2bfloat16(v.x);
    __nv_bfloat16 h1 = __float2bfloat16(v.y);
    __nv_bfloat16 h2 = __float2bfloat16(v.z);
    __nv_bfloat16 h3 = __float2bfloat16(v.w);
    *(__nv_bfloat162*)(hi + i)     = __nv_bfloat162(h0, h1);
    *(__nv_bfloat162*)(hi + i + 2) = __nv_bfloat162(h2, h3);
    *(__nv_bfloat162*)(lo + i)     = __nv_bfloat162(
        __float2bfloat16(v.x - __bfloat162float(h0)),
        __float2bfloat16(v.y - __bfloat162float(h1)));
    *(__nv_bfloat162*)(lo + i + 2) = __nv_bfloat162(
        __float2bfloat16(v.z - __bfloat162float(h2)),
        __float2bfloat16(v.w - __bfloat162float(h3)));
}

// ---------------- HMMA split-bf16 GEMM (LDG prefetch + STS, 2 CTA/SM) ------
// C[M,N] = Ahi.Bhi^T + Ahi.Blo^T + Alo.Bhi^T ; operands [.,1024] K-major bf16.
// CTA tile 128x128, BK=32, 256 threads = 8 warps (4x2), warp tile 32x64.
#define LDAH  40                 // smem row stride in halves (64B data + 16B pad)

__device__ __forceinline__ void gemm_pre(const __nv_bfloat16* __restrict__ Ahi,
                                         const __nv_bfloat16* __restrict__ Alo,
                                         const __nv_bfloat16* __restrict__ Bhi,
                                         const __nv_bfloat16* __restrict__ Blo,
                                         float* __restrict__ C, int N)
{
    __shared__ __align__(16) __nv_bfloat16 Ah[128][LDAH];
    __shared__ __align__(16) __nv_bfloat16 Al[128][LDAH];
    __shared__ __align__(16) __nv_bfloat16 Bh[128][LDAH];
    __shared__ __align__(16) __nv_bfloat16 Bl[128][LDAH];

    const int tid  = threadIdx.x;
    const int lane = tid & 31;
    const int wid  = tid >> 5;
    const int wm   = wid & 3;
    const int wn   = wid >> 2;
    const int gid  = lane >> 2;
    const int tig  = lane & 3;
    const int bm   = blockIdx.y * 128;
    const int bn   = blockIdx.x * 128;

    const int row0 = tid >> 1;             // 0..127
    const int sg0  = (tid & 1) * 2;        // 16B segs {0,1} or {2,3}

    float acc[2][8][4];
#pragma unroll
    for (int i = 0; i < 2; i++)
#pragma unroll
        for (int j = 0; j < 8; j++)
#pragma unroll
            for (int k = 0; k < 4; k++) acc[i][j][k] = 0.0f;

    uint4 pah[2], pal[2], pbh[2], pbl[2];

    auto fetch = [&](int kk) {
#pragma unroll
        for (int i = 0; i < 2; i++) {
            const int ke = kk + (sg0 + i) * 8;
            pah[i] = *(const uint4*)(Ahi + (size_t)(bm + row0) * DM_ + ke);
            pal[i] = *(const uint4*)(Alo + (size_t)(bm + row0) * DM_ + ke);
            pbh[i] = *(const uint4*)(Bhi + (size_t)(bn + row0) * DM_ + ke);
            pbl[i] = *(const uint4*)(Blo + (size_t)(bn + row0) * DM_ + ke);
        }
    };

    fetch(0);

    const int NC = DM_ / 32;               // 32 chunks
    for (int c = 0; c < NC; c++) {
#pragma unroll
        for (int i = 0; i < 2; i++) {
            const int sc = (sg0 + i) * 8;
            *(uint4*)&Ah[row0][sc] = pah[i];
            *(uint4*)&Al[row0][sc] = pal[i];
            *(uint4*)&Bh[row0][sc] = pbh[i];
            *(uint4*)&Bl[row0][sc] = pbl[i];
        }
        __syncthreads();

        if (c + 1 < NC) fetch((c + 1) * 32);   // LDGs ride out during MMAs

#pragma unroll
        for (int ks = 0; ks < 2; ks++) {
            const int kb = ks * 16 + tig * 2;

            uint32_t ah[2][4], al[2][4];
#pragma unroll
            for (int mi = 0; mi < 2; mi++) {
                const int r = wm * 32 + mi * 16 + gid;
                ah[mi][0] = *(const uint32_t*)&Ah[r][kb];
                ah[mi][1] = *(const uint32_t*)&Ah[r + 8][kb];
                ah[mi][2] = *(const uint32_t*)&Ah[r][kb + 8];
                ah[mi][3] = *(const uint32_t*)&Ah[r + 8][kb + 8];
                al[mi][0] = *(const uint32_t*)&Al[r][kb];
                al[mi][1] = *(const uint32_t*)&Al[r + 8][kb];
                al[mi][2] = *(const uint32_t*)&Al[r][kb + 8];
                al[mi][3] = *(const uint32_t*)&Al[r + 8][kb + 8];
            }
#pragma unroll
            for (int ng = 0; ng < 8; ng++) {
                const int rn = wn * 64 + ng * 8 + gid;
                uint32_t bh0 = *(const uint32_t*)&Bh[rn][kb];
                uint32_t bh1 = *(const uint32_t*)&Bh[rn][kb + 8];
                uint32_t bl0 = *(const uint32_t*)&Bl[rn][kb];
                uint32_t bl1 = *(const uint32_t*)&Bl[rn][kb + 8];
                mma16816(acc[0][ng], ah[0], bh0, bh1);
                mma16816(acc[1][ng], ah[1], bh0, bh1);
                mma16816(acc[0][ng], ah[0], bl0, bl1);
                mma16816(acc[1][ng], ah[1], bl0, bl1);
                mma16816(acc[0][ng], al[0], bh0, bh1);
                mma16816(acc[1][ng], al[1], bh0, bh1);
            }
        }
        __syncthreads();
    }

#pragma unroll
    for (int mi = 0; mi < 2; mi++) {
        const int r = bm + wm * 32 + mi * 16 + gid;
#pragma unroll
        for (int ng = 0; ng < 8; ng++) {
            const int col = bn + wn * 64 + ng * 8 + tig * 2;
            *(float2*)&C[(size_t)r * N + col] =
                make_float2(acc[mi][ng][0], acc[mi][ng][1]);
            *(float2*)&C[(size_t)(r + 8) * N + col] =
                make_float2(acc[mi][ng][2], acc[mi][ng][3]);
        }
    }
}

__global__ void __launch_bounds__(256, 2) k_gemm_qkv()
{
    gemm_pre(g_xh, g_xl, g_wqh, g_wql, g_qkv, 3 * DM_);
}

__global__ void __launch_bounds__(256, 2) k_gemm_out(float* __restrict__ out)
{
    gemm_pre(g_aoh, g_aol, g_woh, g_wol, out, DM_);
}

// ---------------- RoPE + bf16 hi/lo split + head layout + V transpose ------
__global__ void __launch_bounds__(256) k_rope(const int* __restrict__ tp)
{
    int idx = blockIdx.x * 256 + threadIdx.x;
    int i = idx & 31;
    int s = (idx >> 5) & (S_ - 1);
    int h = (idx >> 16) & (H_ - 1);
    int b = idx >> 20;

    const int m = b * S_ + s;
    const float* base = g_qkv + (size_t)m * (3 * DM_) + h * DH_;

    float pos = (float)tp[s];
    float inv = powf(10000.0f, -(float)i * (1.0f / 32.0f));
    float ang = pos * inv;
    float sn, cs;
    sincosf(ang, &sn, &cs);

    float qe = base[2 * i],            qo = base[2 * i + 1];
    float ke = base[DM_ + 2 * i],      ko = base[DM_ + 2 * i + 1];
    float ve = base[2 * DM_ + 2 * i],  vo = base[2 * DM_ + 2 * i + 1];

    float rqe = (qe * cs - qo * sn) * 0.125f;
    float rqo = (qo * cs + qe * sn) * 0.125f;
    float rke = ke * cs - ko * sn;
    float rko = ko * cs + ke * sn;

    size_t o = ((size_t)(b * H_ + h) * S_ + s) * DH_ + 2 * i;

    __nv_bfloat16 qh0 = __float2bfloat16(rqe), qh1 = __float2bfloat16(rqo);
    __nv_bfloat16 kh0 = __float2bfloat16(rke), kh1 = __float2bfloat16(rko);
    *(__nv_bfloat162*)&g_qhi[o] = __nv_bfloat162(qh0, qh1);
    *(__nv_bfloat162*)&g_qlo[o] = __nv_bfloat162(
        __float2bfloat16(rqe - __bfloat162float(qh0)),
        __float2bfloat16(rqo - __bfloat162float(qh1)));
    *(__nv_bfloat162*)&g_khi[o] = __nv_bfloat162(kh0, kh1);
    *(__nv_bfloat162*)&g_klo[o] = __nv_bfloat162(
        __float2bfloat16(rke - __bfloat162float(kh0)),
        __float2bfloat16(rko - __bfloat162float(kh1)));

    // V transpose via smem: block = one (b,h), 8 consecutive s
    __shared__ __nv_bfloat16 svh[64][10], svl[64][10];
    const int sl = (threadIdx.x >> 5) & 7;
    __nv_bfloat16 vh0 = __float2bfloat16(ve), vh1 = __float2bfloat16(vo);
    svh[2 * i][sl]     = vh0;
    svh[2 * i + 1][sl] = vh1;
    svl[2 * i][sl]     = __float2bfloat16(ve - __bfloat162float(vh0));
    svl[2 * i + 1][sl] = __float2bfloat16(vo - __bfloat162float(vh1));
    __syncthreads();

    if (threadIdx.x < 128) {
        const int s0  = (blockIdx.x * 8) & (S_ - 1);
        const int idx0 = blockIdx.x * 256;
        const int h0  = (idx0 >> 16) & (H_ - 1);
        const int b0  = idx0 >> 20;
        const int bh  = b0 * H_ + h0;
        const int d   = threadIdx.x >> 1;
        const int sg  = (threadIdx.x & 1) * 4;

        unsigned short uh[4], ul[4];
#pragma unroll
        for (int j = 0; j < 4; j++) {
            uh[j] = *(unsigned short*)&svh[d][sg + j];
            ul[j] = *(unsigned short*)&svl[d][sg + j];
        }
        size_t vo_ = ((size_t)bh * DH_ + d) * S_ + s0 + sg;
        *(uint2*)&g_vthi[vo_] = *(uint2*)uh;
        *(uint2*)&g_vtlo[vo_] = *(uint2*)ul;
    }
}

// ---------------- HMMA flash attention (split-bf16, causal; R7-proven) -----
// grid (S/64, B*H), 128 threads = 4 warps; warp = 16 q-rows, key tiles of 64.
#define LDK 72

__global__ void __launch_bounds__(128) k_attn_mma()
{
    const int bh  = blockIdx.y;
    const int q0  = blockIdx.x * 64;
    const int tid = threadIdx.x;
    const int lane = tid & 31;
    const int w    = tid >> 5;
    const int gid  = lane >> 2;
    const int tig  = lane & 3;

    __shared__ __align__(16) __nv_bfloat16 Khi[64][LDK], Klo[64][LDK];
    __shared__ __align__(16) __nv_bfloat16 Vth[64][LDK], Vtl[64][LDK];

    const __nv_bfloat16* qhi = g_qhi + (size_t)bh * S_ * DH_;
    const __nv_bfloat16* qlo = g_qlo + (size_t)bh * S_ * DH_;
    const __nv_bfloat16* khi = g_khi + (size_t)bh * S_ * DH_;
    const __nv_bfloat16* klo = g_klo + (size_t)bh * S_ * DH_;
    const __nv_bfloat16* vth = g_vthi + (size_t)bh * DH_ * S_;
    const __nv_bfloat16* vtl = g_vtlo + (size_t)bh * DH_ * S_;

    const int row0 = tid >> 1;            // 0..63
    const int seg0 = (tid & 1) * 4;       // 16B segs {0..3} or {4..7}

    // ---- stage Q tile (reuse K smem), extract fragments ----
#pragma unroll
    for (int i2 = 0; i2 < 4; i2++) {
        *(uint4*)&Khi[row0][(seg0 + i2) * 8] =
            *(const uint4*)(qhi + (size_t)(q0 + row0) * DH_ + (seg0 + i2) * 8);
        *(uint4*)&Klo[row0][(seg0 + i2) * 8] =
            *(const uint4*)(qlo + (size_t)(q0 + row0) * DH_ + (seg0 + i2) * 8);
    }
    __syncthreads();

    uint32_t qh[4][4], ql[4][4];
    const int r = w * 16 + gid;
#pragma unroll
    for (int kb = 0; kb < 4; kb++) {
        const int kbase = kb * 16 + tig * 2;
        qh[kb][0] = *(const uint32_t*)&Khi[r][kbase];
        qh[kb][1] = *(const uint32_t*)&Khi[r + 8][kbase];
        qh[kb][2] = *(const uint32_t*)&Khi[r][kbase + 8];
        qh[kb][3] = *(const uint32_t*)&Khi[r + 8][kbase + 8];
        ql[kb][0] = *(const uint32_t*)&Klo[r][kbase];
        ql[kb][1] = *(const uint32_t*)&Klo[r + 8][kbase];
        ql[kb][2] = *(const uint32_t*)&Klo[r][kbase + 8];
        ql[kb][3] = *(const uint32_t*)&Klo[r + 8][kbase + 8];
    }
    __syncthreads();

    float o[8][4];
#pragma unroll
    for (int j = 0; j < 8; j++)
#pragma unroll
        for (int c = 0; c < 4; c++) o[j][c] = 0.0f;
    float m0 = -INFINITY, m1 = -INFINITY, l0 = 0.0f, l1 = 0.0f;

    const int r0a = q0 + w * 16 + gid;

    for (int kt = 0; kt <= q0; kt += 64) {
#pragma unroll
        for (int i2 = 0; i2 < 4; i2++) {
            const int sg = (seg0 + i2) * 8;
            *(uint4*)&Khi[row0][sg] =
                *(const uint4*)(khi + (size_t)(kt + row0) * DH_ + sg);
            *(uint4*)&Klo[row0][sg] =
                *(const uint4*)(klo + (size_t)(kt + row0) * DH_ + sg);
            *(uint4*)&Vth[row0][sg] =
                *(const uint4*)(vth + (size_t)row0 * S_ + kt + sg);
            *(uint4*)&Vtl[row0][sg] =
                *(const uint4*)(vtl + (size_t)row0 * S_ + kt + sg);
        }
        __syncthreads();

        // ---- scores: S = Qhi.Khi + Qhi.Klo + Qlo.Khi ----
        float s[8][4];
#pragma unroll
        for (int j = 0; j < 8; j++)
#pragma unroll
            for (int c = 0; c < 4; c++) s[j][c] = 0.0f;

#pragma unroll
        for (int kb = 0; kb < 4; kb++) {
            const int kbase = kb * 16 + tig * 2;
#pragma unroll
            for (int j = 0; j < 8; j++) {
                const int rn = j * 8 + gid;
                uint32_t kh0 = *(const uint32_t*)&Khi[rn][kbase];
                uint32_t kh1 = *(const uint32_t*)&Khi[rn][kbase + 8];
                uint32_t kl0 = *(const uint32_t*)&Klo[rn][kbase];
                uint32_t kl1 = *(const uint32_t*)&Klo[rn][kbase + 8];
                mma16816(s[j], qh[kb], kh0, kh1);
                mma16816(s[j], qh[kb], kl0, kl1);
                mma16816(s[j], ql[kb], kh0, kh1);
            }
        }

        // ---- causal mask (diagonal block only) ----
        if (kt == q0) {
#pragma unroll
            for (int j = 0; j < 8; j++) {
                const int cb = kt + j * 8 + 2 * tig;
                if (cb     > r0a)     s[j][0] = -INFINITY;
                if (cb + 1 > r0a)     s[j][1] = -INFINITY;
                if (cb     > r0a + 8) s[j][2] = -INFINITY;
                if (cb + 1 > r0a + 8) s[j][3] = -INFINITY;
            }
        }

        // ---- online softmax ----
        float tm0 = m0, tm1 = m1;
#pragma unroll
        for (int j = 0; j < 8; j++) {
            tm0 = fmaxf(tm0, fmaxf(s[j][0], s[j][1]));
            tm1 = fmaxf(tm1, fmaxf(s[j][2], s[j][3]));
        }
        tm0 = fmaxf(tm0, __shfl_xor_sync(0xffffffff, tm0, 1));
        tm0 = fmaxf(tm0, __shfl_xor_sync(0xffffffff, tm0, 2));
        tm1 = fmaxf(tm1, __shfl_xor_sync(0xffffffff, tm1, 1));
        tm1 = fmaxf(tm1, __shfl_xor_sync(0xffffffff, tm1, 2));

        const float sc0 = __expf(m0 - tm0);
        const float sc1 = __expf(m1 - tm1);
        m0 = tm0; m1 = tm1;
        l0 *= sc0; l1 *= sc1;
#pragma unroll
        for (int j = 0; j < 8; j++) {
            o[j][0] *= sc0; o[j][1] *= sc0;
            o[j][2] *= sc1; o[j][3] *= sc1;
        }

        float rs0 = 0.0f, rs1 = 0.0f;
#pragma unroll
        for (int j = 0; j < 8; j++) {
            s[j][0] = __expf(s[j][0] - m0);
            s[j][1] = __expf(s[j][1] - m0);
            s[j][2] = __expf(s[j][2] - m1);
            s[j][3] = __expf(s[j][3] - m1);
            rs0 += s[j][0] + s[j][1];
            rs1 += s[j][2] + s[j][3];
        }
        rs0 += __shfl_xor_sync(0xffffffff, rs0, 1);
        rs0 += __shfl_xor_sync(0xffffffff, rs0, 2);
        rs1 += __shfl_xor_sync(0xffffffff, rs1, 1);
        rs1 += __shfl_xor_sync(0xffffffff, rs1, 2);
        l0 += rs0; l1 += rs1;

        // ---- P into A-fragments (hi/lo) ----
        uint32_t ph[4][4], pl[4][4];
#pragma unroll
        for (int kb = 0; kb < 4; kb++) {
            const int j0 = 2 * kb, j1 = 2 * kb + 1;
            ph[kb][0] = pack_bf16(s[j0][0], s[j0][1]);
            ph[kb][1] = pack_bf16(s[j0][2], s[j0][3]);
            ph[kb][2] = pack_bf16(s[j1][0], s[j1][1]);
            ph[kb][3] = pack_bf16(s[j1][2], s[j1][3]);
            __nv_bfloat162 h0 = *(__nv_bfloat162*)&ph[kb][0];
            __nv_bfloat162 h1 = *(__nv_bfloat162*)&ph[kb][1];
            __nv_bfloat162 h2 = *(__nv_bfloat162*)&ph[kb][2];
            __nv_bfloat162 h3 = *(__nv_bfloat162*)&ph[kb][3];
            pl[kb][0] = pack_bf16(s[j0][0] - __bfloat162float(h0.x),
                                  s[j0][1] - __bfloat162float(h0.y));
            pl[kb][1] = pack_bf16(s[j0][2] - __bfloat162float(h1.x),
                                  s[j0][3] - __bfloat162float(h1.y));
            pl[kb][2] = pack_bf16(s[j1][0] - __bfloat162float(h2.x),
                                  s[j1][1] - __bfloat162float(h2.y));
            pl[kb][3] = pack_bf16(s[j1][2] - __bfloat162float(h3.x),
                                  s[j1][3] - __bfloat162float(h3.y));
        }

        // ---- O += P.V ----
#pragma unroll
        for (int kb = 0; kb < 4; kb++) {
            const int kbase = kb * 16 + tig * 2;
#pragma unroll
            for (int j = 0; j < 8; j++) {
                const int rn = j * 8 + gid;
                uint32_t vh0 = *(const uint32_t*)&Vth[rn][kbase];
                uint32_t vh1 = *(const uint32_t*)&Vth[rn][kbase + 8];
                uint32_t vl0 = *(const uint32_t*)&Vtl[rn][kbase];
                uint32_t vl1 = *(const uint32_t*)&Vtl[rn][kbase + 8];
                mma16816(o[j], ph[kb], vh0, vh1);
                mma16816(o[j], ph[kb], vl0, vl1);
                mma16816(o[j], pl[kb], vh0, vh1);
            }
        }
        __syncthreads();
    }

    // ---- epilogue ----
    const float inv0 = 1.0f / l0;
    const float inv1 = 1.0f / l1;
    const int b = bh >> 4, h = bh & 15;
#pragma unroll
    for (int j = 0; j < 8; j++) {
        const int col = h * DH_ + j * 8 + 2 * tig;
        *(float2*)&g_ao[(size_t)(b * S_ + r0a) * DM_ + col] =
            make_float2(o[j][0] * inv0, o[j][1] * inv0);
        *(float2*)&g_ao[(size_t)(b * S_ + r0a + 8) * DM_ + col] =
            make_float2(o[j][2] * inv1, o[j][3] * inv1);
    }
}

// ---------------- launch ----------------
extern "C" void kernel_launch(void* const* d_in, const int* in_sizes, int n_in,
                              void* d_out, int out_size)
{
    const float* x      = (const float*)d_in[0];
    const float* w_qkv  = (const float*)d_in[1];
    const float* w_o    = (const float*)d_in[2];
    const int*   tp     = (const int*)d_in[3];

    // 0) one-time bf16 hi/lo splits of x, w_qkv, w_o
    k_splitg<<<(MTOK * DM_) / 1024, 256>>>(x, 0);
    k_splitg<<<(3 * DM_ * DM_) / 1024, 256>>>(w_qkv, 1);
    k_splitg<<<(DM_ * DM_) / 1024, 256>>>(w_o, 2);

    // 1) QKV projection (HMMA, pre-split operands, 2 CTA/SM)
    k_gemm_qkv<<<dim3(3 * DM_ / 128, MTOK / 128), 256>>>();

    // 2) RoPE + bf16 hi/lo per-head layout + V transpose
    k_rope<<<(B_ * H_ * S_ * 32) / 256, 256>>>(tp);

    // 3) causal flash attention (HMMA split-bf16)
    k_attn_mma<<<dim3(S_ / 64, B_ * H_), 128>>>();

    // 4) split attention output, output projection
    k_splitg<<<(MTOK * DM_) / 1024, 256>>>(nullptr, 3);
    k_gemm_out<<<dim3(DM_ / 128, MTOK / 128), 256>>>((float*)d_out);
}

// round 10
// speedup vs baseline: 1.5562x; 1.1141x over previous
#include <cuda_runtime.h>
#include <cuda_bf16.h>
#include <cstdint>
#include <math.h>

#define B_   2
#define S_   2048
#define H_   16
#define DH_  64
#define DM_  1024
#define MTOK (B_ * S_)        // 4096

// ---------------- scratch (device-code references ONLY) ----------------
__device__ float g_qkv[(size_t)MTOK * 3 * DM_];     // 48 MB
__device__ float g_ao [(size_t)MTOK * DM_];         // 16 MB

// bf16 hi/lo GEMM operands
__device__ __nv_bfloat16 g_xh [(size_t)MTOK * DM_];
__device__ __nv_bfloat16 g_xl [(size_t)MTOK * DM_];
__device__ __nv_bfloat16 g_wqh[(size_t)3 * DM_ * DM_];
__device__ __nv_bfloat16 g_wql[(size_t)3 * DM_ * DM_];
__device__ __nv_bfloat16 g_woh[(size_t)DM_ * DM_];
__device__ __nv_bfloat16 g_wol[(size_t)DM_ * DM_];
__device__ __nv_bfloat16 g_aoh[(size_t)MTOK * DM_];
__device__ __nv_bfloat16 g_aol[(size_t)MTOK * DM_];

// bf16 hi/lo attention operands (Q has 0.125 score scale folded in)
__device__ __nv_bfloat16 g_qhi[(size_t)B_ * H_ * S_ * DH_];
__device__ __nv_bfloat16 g_qlo[(size_t)B_ * H_ * S_ * DH_];
__device__ __nv_bfloat16 g_khi[(size_t)B_ * H_ * S_ * DH_];
__device__ __nv_bfloat16 g_klo[(size_t)B_ * H_ * S_ * DH_];
__device__ __nv_bfloat16 g_vthi[(size_t)B_ * H_ * DH_ * S_];  // transposed [bh][d][s]
__device__ __nv_bfloat16 g_vtlo[(size_t)B_ * H_ * DH_ * S_];

// ---------------- helpers ----------------
__device__ __forceinline__ uint32_t smem_u32(const void* p) {
    uint32_t a;
    asm("{ .reg .u64 t; cvta.to.shared.u64 t, %1; cvt.u32.u64 %0, t; }"
        : "=r"(a) : "l"(p));
    return a;
}

__device__ __forceinline__ void mma16816(float* d, const uint32_t* a,
                                         uint32_t b0, uint32_t b1) {
    asm volatile(
        "mma.sync.aligned.m16n8k16.row.col.f32.bf16.bf16.f32 "
        "{%0,%1,%2,%3}, {%4,%5,%6,%7}, {%8,%9}, {%0,%1,%2,%3};"
        : "+f"(d[0]), "+f"(d[1]), "+f"(d[2]), "+f"(d[3])
        : "r"(a[0]), "r"(a[1]), "r"(a[2]), "r"(a[3]), "r"(b0), "r"(b1));
}

__device__ __forceinline__ void ldsm4(uint32_t& r0, uint32_t& r1,
                                      uint32_t& r2, uint32_t& r3, uint32_t addr) {
    asm volatile("ldmatrix.sync.aligned.m8n8.x4.shared.b16 {%0,%1,%2,%3}, [%4];"
                 : "=r"(r0), "=r"(r1), "=r"(r2), "=r"(r3) : "r"(addr));
}

__device__ __forceinline__ uint32_t pack_bf16(float x, float y) {
    __nv_bfloat162 t(__float2bfloat16(x), __float2bfloat16(y));
    return *(uint32_t*)&t;
}

// ---------------- fp32 -> bf16 hi/lo split (one-time, streaming) ----------
__global__ void __launch_bounds__(256) k_splitg(const float* __restrict__ in,
                                                int which)
{
    __nv_bfloat16 *hi, *lo;
    if      (which == 0) { hi = g_xh;  lo = g_xl;  }
    else if (which == 1) { hi = g_wqh; lo = g_wql; }
    else if (which == 2) { hi = g_woh; lo = g_wol; }
    else                 { hi = g_aoh; lo = g_aol; in = g_ao; }

    int i = (blockIdx.x * 256 + threadIdx.x) * 4;
    float4 v = *(const float4*)(in + i);
    __nv_bfloat16 h0 = __float2bfloat16(v.x);
    __nv_bfloat16 h1 = __float2bfloat16(v.y);
    __nv_bfloat16 h2 = __float2bfloat16(v.z);
    __nv_bfloat16 h3 = __float2bfloat16(v.w);
    *(__nv_bfloat162*)(hi + i)     = __nv_bfloat162(h0, h1);
    *(__nv_bfloat162*)(hi + i + 2) = __nv_bfloat162(h2, h3);
    *(__nv_bfloat162*)(lo + i)     = __nv_bfloat162(
        __float2bfloat16(v.x - __bfloat162float(h0)),
        __float2bfloat16(v.y - __bfloat162float(h1)));
    *(__nv_bfloat162*)(lo + i + 2) = __nv_bfloat162(
        __float2bfloat16(v.z - __bfloat162float(h2)),
        __float2bfloat16(v.w - __bfloat162float(h3)));
}

// ---------------- HMMA split-bf16 GEMM (ldmatrix fragments) ----------------
// C[M,N] = Ahi.Bhi^T + Ahi.Blo^T + Alo.Bhi^T ; operands [.,1024] K-major bf16.
// CTA tile 128x128, BK=32, 256 threads = 8 warps (4x2), warp tile 32x64.
#define LDAH  40                 // smem row stride in halves (80 B: 8 distinct 16B phases)

__device__ __forceinline__ void gemm_pre(const __nv_bfloat16* __restrict__ Ahi,
                                         const __nv_bfloat16* __restrict__ Alo,
                                         const __nv_bfloat16* __restrict__ Bhi,
                                         const __nv_bfloat16* __restrict__ Blo,
                                         float* __restrict__ C, int N)
{
    __shared__ __align__(16) __nv_bfloat16 Ah[128][LDAH];
    __shared__ __align__(16) __nv_bfloat16 Al[128][LDAH];
    __shared__ __align__(16) __nv_bfloat16 Bh[128][LDAH];
    __shared__ __align__(16) __nv_bfloat16 Bl[128][LDAH];

    const int tid  = threadIdx.x;
    const int lane = tid & 31;
    const int wid  = tid >> 5;
    const int wm   = wid & 3;
    const int wn   = wid >> 2;
    const int gid  = lane >> 2;
    const int tig  = lane & 3;
    const int bm   = blockIdx.y * 128;
    const int bn   = blockIdx.x * 128;

    // ldmatrix lane roles
    const int lr   = lane & 7;
    const int qd   = lane >> 3;              // quadrant 0..3
    const int arow = (qd & 1) * 8 + lr;      // A atom: q0=r0c0 q1=r8c0 q2=r0c8 q3=r8c8
    const int acol = (qd >> 1) * 8;
    const int brow = (qd >> 1) * 8 + lr;     // B pair: q0=(j0,klo) q1=(j0,khi) q2=(j1,klo) q3=(j1,khi)
    const int bcol = (qd & 1) * 8;

    const uint32_t ah_b = smem_u32(&Ah[0][0]);
    const uint32_t al_b = smem_u32(&Al[0][0]);
    const uint32_t bh_b = smem_u32(&Bh[0][0]);
    const uint32_t bl_b = smem_u32(&Bl[0][0]);

    const int row0 = tid >> 1;             // 0..127
    const int sg0  = (tid & 1) * 2;        // 16B segs {0,1} or {2,3}

    float acc[2][8][4];
#pragma unroll
    for (int i = 0; i < 2; i++)
#pragma unroll
        for (int j = 0; j < 8; j++)
#pragma unroll
            for (int k = 0; k < 4; k++) acc[i][j][k] = 0.0f;

    uint4 pah[2], pal[2], pbh[2], pbl[2];

    auto fetch = [&](int kk) {
#pragma unroll
        for (int i = 0; i < 2; i++) {
            const int ke = kk + (sg0 + i) * 8;
            pah[i] = *(const uint4*)(Ahi + (size_t)(bm + row0) * DM_ + ke);
            pal[i] = *(const uint4*)(Alo + (size_t)(bm + row0) * DM_ + ke);
            pbh[i] = *(const uint4*)(Bhi + (size_t)(bn + row0) * DM_ + ke);
            pbl[i] = *(const uint4*)(Blo + (size_t)(bn + row0) * DM_ + ke);
        }
    };

    fetch(0);

    const int NC = DM_ / 32;               // 32 chunks
    for (int c = 0; c < NC; c++) {
#pragma unroll
        for (int i = 0; i < 2; i++) {
            const int sc = (sg0 + i) * 8;
            *(uint4*)&Ah[row0][sc] = pah[i];
            *(uint4*)&Al[row0][sc] = pal[i];
            *(uint4*)&Bh[row0][sc] = pbh[i];
            *(uint4*)&Bl[row0][sc] = pbl[i];
        }
        __syncthreads();

        if (c + 1 < NC) fetch((c + 1) * 32);   // LDGs ride out during MMAs

#pragma unroll
        for (int ks = 0; ks < 2; ks++) {
            uint32_t ah[2][4], al[2][4];
#pragma unroll
            for (int mi = 0; mi < 2; mi++) {
                const uint32_t off =
                    (uint32_t)((wm * 32 + mi * 16 + arow) * LDAH + ks * 16 + acol) * 2;
                ldsm4(ah[mi][0], ah[mi][1], ah[mi][2], ah[mi][3], ah_b + off);
                ldsm4(al[mi][0], al[mi][1], al[mi][2], al[mi][3], al_b + off);
            }
#pragma unroll
            for (int pg = 0; pg < 4; pg++) {
                const uint32_t off =
                    (uint32_t)((wn * 64 + pg * 16 + brow) * LDAH + ks * 16 + bcol) * 2;
                uint32_t bh0, bh1, bh2, bh3, bl0, bl1, bl2, bl3;
                ldsm4(bh0, bh1, bh2, bh3, bh_b + off);
                ldsm4(bl0, bl1, bl2, bl3, bl_b + off);
                const int n0 = pg * 2, n1 = pg * 2 + 1;
                mma16816(acc[0][n0], ah[0], bh0, bh1);
                mma16816(acc[1][n0], ah[1], bh0, bh1);
                mma16816(acc[0][n0], ah[0], bl0, bl1);
                mma16816(acc[1][n0], ah[1], bl0, bl1);
                mma16816(acc[0][n0], al[0], bh0, bh1);
                mma16816(acc[1][n0], al[1], bh0, bh1);
                mma16816(acc[0][n1], ah[0], bh2, bh3);
                mma16816(acc[1][n1], ah[1], bh2, bh3);
                mma16816(acc[0][n1], ah[0], bl2, bl3);
                mma16816(acc[1][n1], ah[1], bl2, bl3);
                mma16816(acc[0][n1], al[0], bh2, bh3);
                mma16816(acc[1][n1], al[1], bh2, bh3);
            }
        }
        __syncthreads();
    }

#pragma unroll
    for (int mi = 0; mi < 2; mi++) {
        const int r = bm + wm * 32 + mi * 16 + gid;
#pragma unroll
        for (int ng = 0; ng < 8; ng++) {
            const int col = bn + wn * 64 + ng * 8 + tig * 2;
            *(float2*)&C[(size_t)r * N + col] =
                make_float2(acc[mi][ng][0], acc[mi][ng][1]);
            *(float2*)&C[(size_t)(r + 8) * N + col] =
                make_float2(acc[mi][ng][2], acc[mi][ng][3]);
        }
    }
}

__global__ void __launch_bounds__(256, 2) k_gemm_qkv()
{
    gemm_pre(g_xh, g_xl, g_wqh, g_wql, g_qkv, 3 * DM_);
}

__global__ void __launch_bounds__(256, 2) k_gemm_out(float* __restrict__ out)
{
    gemm_pre(g_aoh, g_aol, g_woh, g_wol, out, DM_);
}

// ---------------- RoPE + bf16 hi/lo split + head layout + V transpose ------
__global__ void __launch_bounds__(256) k_rope(const int* __restrict__ tp)
{
    int idx = blockIdx.x * 256 + threadIdx.x;
    int i = idx & 31;
    int s = (idx >> 5) & (S_ - 1);
    int h = (idx >> 16) & (H_ - 1);
    int b = idx >> 20;

    const int m = b * S_ + s;
    const float* base = g_qkv + (size_t)m * (3 * DM_) + h * DH_;

    float pos = (float)tp[s];
    float inv = powf(10000.0f, -(float)i * (1.0f / 32.0f));
    float ang = pos * inv;
    float sn, cs;
    sincosf(ang, &sn, &cs);

    float qe = base[2 * i],            qo = base[2 * i + 1];
    float ke = base[DM_ + 2 * i],      ko = base[DM_ + 2 * i + 1];
    float ve = base[2 * DM_ + 2 * i],  vo = base[2 * DM_ + 2 * i + 1];

    float rqe = (qe * cs - qo * sn) * 0.125f;
    float rqo = (qo * cs + qe * sn) * 0.125f;
    float rke = ke * cs - ko * sn;
    float rko = ko * cs + ke * sn;

    size_t o = ((size_t)(b * H_ + h) * S_ + s) * DH_ + 2 * i;

    __nv_bfloat16 qh0 = __float2bfloat16(rqe), qh1 = __float2bfloat16(rqo);
    __nv_bfloat16 kh0 = __float2bfloat16(rke), kh1 = __float2bfloat16(rko);
    *(__nv_bfloat162*)&g_qhi[o] = __nv_bfloat162(qh0, qh1);
    *(__nv_bfloat162*)&g_qlo[o] = __nv_bfloat162(
        __float2bfloat16(rqe - __bfloat162float(qh0)),
        __float2bfloat16(rqo - __bfloat162float(qh1)));
    *(__nv_bfloat162*)&g_khi[o] = __nv_bfloat162(kh0, kh1);
    *(__nv_bfloat162*)&g_klo[o] = __nv_bfloat162(
        __float2bfloat16(rke - __bfloat162float(kh0)),
        __float2bfloat16(rko - __bfloat162float(kh1)));

    // V transpose via smem: block = one (b,h), 8 consecutive s
    __shared__ __nv_bfloat16 svh[64][10], svl[64][10];
    const int sl = (threadIdx.x >> 5) & 7;
    __nv_bfloat16 vh0 = __float2bfloat16(ve), vh1 = __float2bfloat16(vo);
    svh[2 * i][sl]     = vh0;
    svh[2 * i + 1][sl] = vh1;
    svl[2 * i][sl]     = __float2bfloat16(ve - __bfloat162float(vh0));
    svl[2 * i + 1][sl] = __float2bfloat16(vo - __bfloat162float(vh1));
    __syncthreads();

    if (threadIdx.x < 128) {
        const int s0  = (blockIdx.x * 8) & (S_ - 1);
        const int idx0 = blockIdx.x * 256;
        const int h0  = (idx0 >> 16) & (H_ - 1);
        const int b0  = idx0 >> 20;
        const int bh  = b0 * H_ + h0;
        const int d   = threadIdx.x >> 1;
        const int sg  = (threadIdx.x & 1) * 4;

        unsigned short uh[4], ul[4];
#pragma unroll
        for (int j = 0; j < 4; j++) {
            uh[j] = *(unsigned short*)&svh[d][sg + j];
            ul[j] = *(unsigned short*)&svl[d][sg + j];
        }
        size_t vo_ = ((size_t)bh * DH_ + d) * S_ + s0 + sg;
        *(uint2*)&g_vthi[vo_] = *(uint2*)uh;
        *(uint2*)&g_vtlo[vo_] = *(uint2*)ul;
    }
}

// ---------------- HMMA flash attention (split-bf16, causal, ldmatrix) ------
// grid (S/64, B*H), 128 threads = 4 warps; warp = 16 q-rows, key tiles of 64.
#define LDK 72     // 144 B stride: 8 distinct 16B phases -> conflict-free ldmatrix

__global__ void __launch_bounds__(128) k_attn_mma()
{
    const int bh  = blockIdx.y;
    const int q0  = blockIdx.x * 64;
    const int tid = threadIdx.x;
    const int lane = tid & 31;
    const int w    = tid >> 5;
    const int gid  = lane >> 2;
    const int tig  = lane & 3;

    // ldmatrix lane roles (same derivation as GEMM)
    const int lr   = lane & 7;
    const int qd   = lane >> 3;
    const int arow = (qd & 1) * 8 + lr;
    const int acol = (qd >> 1) * 8;
    const int brow = (qd >> 1) * 8 + lr;
    const int bcol = (qd & 1) * 8;

    __shared__ __align__(16) __nv_bfloat16 Khi[64][LDK], Klo[64][LDK];
    __shared__ __align__(16) __nv_bfloat16 Vth[64][LDK], Vtl[64][LDK];

    const uint32_t kh_b = smem_u32(&Khi[0][0]);
    const uint32_t kl_b = smem_u32(&Klo[0][0]);
    const uint32_t vh_b = smem_u32(&Vth[0][0]);
    const uint32_t vl_b = smem_u32(&Vtl[0][0]);

    const __nv_bfloat16* qhi = g_qhi + (size_t)bh * S_ * DH_;
    const __nv_bfloat16* qlo = g_qlo + (size_t)bh * S_ * DH_;
    const __nv_bfloat16* khi = g_khi + (size_t)bh * S_ * DH_;
    const __nv_bfloat16* klo = g_klo + (size_t)bh * S_ * DH_;
    const __nv_bfloat16* vth = g_vthi + (size_t)bh * DH_ * S_;
    const __nv_bfloat16* vtl = g_vtlo + (size_t)bh * DH_ * S_;

    const int row0 = tid >> 1;            // 0..63
    const int seg0 = (tid & 1) * 4;       // 16B segs {0..3} or {4..7}

    // ---- stage Q tile (reuse K smem), extract fragments via ldmatrix ----
#pragma unroll
    for (int i2 = 0; i2 < 4; i2++) {
        *(uint4*)&Khi[row0][(seg0 + i2) * 8] =
            *(const uint4*)(qhi + (size_t)(q0 + row0) * DH_ + (seg0 + i2) * 8);
        *(uint4*)&Klo[row0][(seg0 + i2) * 8] =
            *(const uint4*)(qlo + (size_t)(q0 + row0) * DH_ + (seg0 + i2) * 8);
    }
    __syncthreads();

    uint32_t qh[4][4], ql[4][4];
#pragma unroll
    for (int kb = 0; kb < 4; kb++) {
        const uint32_t off =
            (uint32_t)((w * 16 + arow) * LDK + kb * 16 + acol) * 2;
        ldsm4(qh[kb][0], qh[kb][1], qh[kb][2], qh[kb][3], kh_b + off);
        ldsm4(ql[kb][0], ql[kb][1], ql[kb][2], ql[kb][3], kl_b + off);
    }
    __syncthreads();

    float o[8][4];
#pragma unroll
    for (int j = 0; j < 8; j++)
#pragma unroll
        for (int c = 0; c < 4; c++) o[j][c] = 0.0f;
    float m0 = -INFINITY, m1 = -INFINITY, l0 = 0.0f, l1 = 0.0f;

    const int r0a = q0 + w * 16 + gid;

    for (int kt = 0; kt <= q0; kt += 64) {
#pragma unroll
        for (int i2 = 0; i2 < 4; i2++) {
            const int sg = (seg0 + i2) * 8;
            *(uint4*)&Khi[row0][sg] =
                *(const uint4*)(khi + (size_t)(kt + row0) * DH_ + sg);
            *(uint4*)&Klo[row0][sg] =
                *(const uint4*)(klo + (size_t)(kt + row0) * DH_ + sg);
            *(uint4*)&Vth[row0][sg] =
                *(const uint4*)(vth + (size_t)row0 * S_ + kt + sg);
            *(uint4*)&Vtl[row0][sg] =
                *(const uint4*)(vtl + (size_t)row0 * S_ + kt + sg);
        }
        __syncthreads();

        // ---- scores: S = Qhi.Khi + Qhi.Klo + Qlo.Khi ----
        float s[8][4];
#pragma unroll
        for (int j = 0; j < 8; j++)
#pragma unroll
            for (int c = 0; c < 4; c++) s[j][c] = 0.0f;

#pragma unroll
        for (int kb = 0; kb < 4; kb++) {
#pragma unroll
            for (int jp = 0; jp < 4; jp++) {
                const uint32_t off =
                    (uint32_t)((jp * 16 + brow) * LDK + kb * 16 + bcol) * 2;
                uint32_t kh0, kh1, kh2, kh3, kl0, kl1, kl2, kl3;
                ldsm4(kh0, kh1, kh2, kh3, kh_b + off);
                ldsm4(kl0, kl1, kl2, kl3, kl_b + off);
                const int j0 = jp * 2, j1 = jp * 2 + 1;
                mma16816(s[j0], qh[kb], kh0, kh1);
                mma16816(s[j0], qh[kb], kl0, kl1);
                mma16816(s[j0], ql[kb], kh0, kh1);
                mma16816(s[j1], qh[kb], kh2, kh3);
                mma16816(s[j1], qh[kb], kl2, kl3);
                mma16816(s[j1], ql[kb], kh2, kh3);
            }
        }

        // ---- causal mask (diagonal block only) ----
        if (kt == q0) {
#pragma unroll
            for (int j = 0; j < 8; j++) {
                const int cb = kt + j * 8 + 2 * tig;
                if (cb     > r0a)     s[j][0] = -INFINITY;
                if (cb + 1 > r0a)     s[j][1] = -INFINITY;
                if (cb     > r0a + 8) s[j][2] = -INFINITY;
                if (cb + 1 > r0a + 8) s[j][3] = -INFINITY;
            }
        }

        // ---- online softmax ----
        float tm0 = m0, tm1 = m1;
#pragma unroll
        for (int j = 0; j < 8; j++) {
            tm0 = fmaxf(tm0, fmaxf(s[j][0], s[j][1]));
            tm1 = fmaxf(tm1, fmaxf(s[j][2], s[j][3]));
        }
        tm0 = fmaxf(tm0, __shfl_xor_sync(0xffffffff, tm0, 1));
        tm0 = fmaxf(tm0, __shfl_xor_sync(0xffffffff, tm0, 2));
        tm1 = fmaxf(tm1, __shfl_xor_sync(0xffffffff, tm1, 1));
        tm1 = fmaxf(tm1, __shfl_xor_sync(0xffffffff, tm1, 2));

        const float sc0 = __expf(m0 - tm0);
        const float sc1 = __expf(m1 - tm1);
        m0 = tm0; m1 = tm1;
        l0 *= sc0; l1 *= sc1;
#pragma unroll
        for (int j = 0; j < 8; j++) {
            o[j][0] *= sc0; o[j][1] *= sc0;
            o[j][2] *= sc1; o[j][3] *= sc1;
        }

        float rs0 = 0.0f, rs1 = 0.0f;
#pragma unroll
        for (int j = 0; j < 8; j++) {
            s[j][0] = __expf(s[j][0] - m0);
            s[j][1] = __expf(s[j][1] - m0);
            s[j][2] = __expf(s[j][2] - m1);
            s[j][3] = __expf(s[j][3] - m1);
            rs0 += s[j][0] + s[j][1];
            rs1 += s[j][2] + s[j][3];
        }
        rs0 += __shfl_xor_sync(0xffffffff, rs0, 1);
        rs0 += __shfl_xor_sync(0xffffffff, rs0, 2);
        rs1 += __shfl_xor_sync(0xffffffff, rs1, 1);
        rs1 += __shfl_xor_sync(0xffffffff, rs1, 2);
        l0 += rs0; l1 += rs1;

        // ---- P into A-fragments (hi/lo) ----
        uint32_t ph[4][4], pl[4][4];
#pragma unroll
        for (int kb = 0; kb < 4; kb++) {
            const int j0 = 2 * kb, j1 = 2 * kb + 1;
            ph[kb][0] = pack_bf16(s[j0][0], s[j0][1]);
            ph[kb][1] = pack_bf16(s[j0][2], s[j0][3]);
            ph[kb][2] = pack_bf16(s[j1][0], s[j1][1]);
            ph[kb][3] = pack_bf16(s[j1][2], s[j1][3]);
            __nv_bfloat162 h0 = *(__nv_bfloat162*)&ph[kb][0];
            __nv_bfloat162 h1 = *(__nv_bfloat162*)&ph[kb][1];
            __nv_bfloat162 h2 = *(__nv_bfloat162*)&ph[kb][2];
            __nv_bfloat162 h3 = *(__nv_bfloat162*)&ph[kb][3];
            pl[kb][0] = pack_bf16(s[j0][0] - __bfloat162float(h0.x),
                                  s[j0][1] - __bfloat162float(h0.y));
            pl[kb][1] = pack_bf16(s[j0][2] - __bfloat162float(h1.x),
                                  s[j0][3] - __bfloat162float(h1.y));
            pl[kb][2] = pack_bf16(s[j1][0] - __bfloat162float(h2.x),
                                  s[j1][1] - __bfloat162float(h2.y));
            pl[kb][3] = pack_bf16(s[j1][2] - __bfloat162float(h3.x),
                                  s[j1][3] - __bfloat162float(h3.y));
        }

        // ---- O += P.V : Phi.Vhi + Phi.Vlo + Plo.Vhi ----
#pragma unroll
        for (int kb = 0; kb < 4; kb++) {
#pragma unroll
            for (int jp = 0; jp < 4; jp++) {
                const uint32_t off =
                    (uint32_t)((jp * 16 + brow) * LDK + kb * 16 + bcol) * 2;
                uint32_t vh0, vh1, vh2, vh3, vl0, vl1, vl2, vl3;
                ldsm4(vh0, vh1, vh2, vh3, vh_b + off);
                ldsm4(vl0, vl1, vl2, vl3, vl_b + off);
                const int j0 = jp * 2, j1 = jp * 2 + 1;
                mma16816(o[j0], ph[kb], vh0, vh1);
                mma16816(o[j0], ph[kb], vl0, vl1);
                mma16816(o[j0], pl[kb], vh0, vh1);
                mma16816(o[j1], ph[kb], vh2, vh3);
                mma16816(o[j1], ph[kb], vl2, vl3);
                mma16816(o[j1], pl[kb], vh2, vh3);
            }
        }
        __syncthreads();
    }

    // ---- epilogue ----
    const float inv0 = 1.0f / l0;
    const float inv1 = 1.0f / l1;
    const int b = bh >> 4, h = bh & 15;
#pragma unroll
    for (int j = 0; j < 8; j++) {
        const int col = h * DH_ + j * 8 + 2 * tig;
        *(float2*)&g_ao[(size_t)(b * S_ + r0a) * DM_ + col] =
            make_float2(o[j][0] * inv0, o[j][1] * inv0);
        *(float2*)&g_ao[(size_t)(b * S_ + r0a + 8) * DM_ + col] =
            make_float2(o[j][2] * inv1, o[j][3] * inv1);
    }
}

// ---------------- launch ----------------
extern "C" void kernel_launch(void* const* d_in, const int* in_sizes, int n_in,
                              void* d_out, int out_size)
{
    const float* x      = (const float*)d_in[0];
    const float* w_qkv  = (const float*)d_in[1];
    const float* w_o    = (const float*)d_in[2];
    const int*   tp     = (const int*)d_in[3];

    // 0) one-time bf16 hi/lo splits of x, w_qkv, w_o
    k_splitg<<<(MTOK * DM_) / 1024, 256>>>(x, 0);
    k_splitg<<<(3 * DM_ * DM_) / 1024, 256>>>(w_qkv, 1);
    k_splitg<<<(DM_ * DM_) / 1024, 256>>>(w_o, 2);

    // 1) QKV projection (HMMA + ldmatrix)
    k_gemm_qkv<<<dim3(3 * DM_ / 128, MTOK / 128), 256>>>();

    // 2) RoPE + bf16 hi/lo per-head layout + V transpose
    k_rope<<<(B_ * H_ * S_ * 32) / 256, 256>>>(tp);

    // 3) causal flash attention (HMMA + ldmatrix)
    k_attn_mma<<<dim3(S_ / 64, B_ * H_), 128>>>();

    // 4) split attention output, output projection
    k_splitg<<<(MTOK * DM_) / 1024, 256>>>(nullptr, 3);
    k_gemm_out<<<dim3(DM_ / 128, MTOK / 128), 256>>>((float*)d_out);
}

// round 11
// speedup vs baseline: 1.6010x; 1.0288x over previous
#include <cuda_runtime.h>
#include <cuda_bf16.h>
#include <cstdint>
#include <math.h>

#define B_   2
#define S_   2048
#define H_   16
#define DH_  64
#define DM_  1024
#define MTOK (B_ * S_)        // 4096

// ---------------- scratch (device-code references ONLY) ----------------
__device__ float g_qkv[(size_t)MTOK * 3 * DM_];     // 48 MB
__device__ float g_ao [(size_t)MTOK * DM_];         // 16 MB

// bf16 hi/lo GEMM operands
__device__ __nv_bfloat16 g_xh [(size_t)MTOK * DM_];
__device__ __nv_bfloat16 g_xl [(size_t)MTOK * DM_];
__device__ __nv_bfloat16 g_wqh[(size_t)3 * DM_ * DM_];
__device__ __nv_bfloat16 g_wql[(size_t)3 * DM_ * DM_];
__device__ __nv_bfloat16 g_woh[(size_t)DM_ * DM_];
__device__ __nv_bfloat16 g_wol[(size_t)DM_ * DM_];
__device__ __nv_bfloat16 g_aoh[(size_t)MTOK * DM_];
__device__ __nv_bfloat16 g_aol[(size_t)MTOK * DM_];

// bf16 hi/lo attention operands (Q has 0.125 score scale folded in)
__device__ __nv_bfloat16 g_qhi[(size_t)B_ * H_ * S_ * DH_];
__device__ __nv_bfloat16 g_qlo[(size_t)B_ * H_ * S_ * DH_];
__device__ __nv_bfloat16 g_khi[(size_t)B_ * H_ * S_ * DH_];
__device__ __nv_bfloat16 g_klo[(size_t)B_ * H_ * S_ * DH_];
__device__ __nv_bfloat16 g_vthi[(size_t)B_ * H_ * DH_ * S_];  // transposed [bh][d][s]
__device__ __nv_bfloat16 g_vtlo[(size_t)B_ * H_ * DH_ * S_];

// ---------------- helpers ----------------
__device__ __forceinline__ uint32_t smem_u32(const void* p) {
    uint32_t a;
    asm("{ .reg .u64 t; cvta.to.shared.u64 t, %1; cvt.u32.u64 %0, t; }"
        : "=r"(a) : "l"(p));
    return a;
}

__device__ __forceinline__ void mma16816(float* d, const uint32_t* a,
                                         uint32_t b0, uint32_t b1) {
    asm volatile(
        "mma.sync.aligned.m16n8k16.row.col.f32.bf16.bf16.f32 "
        "{%0,%1,%2,%3}, {%4,%5,%6,%7}, {%8,%9}, {%0,%1,%2,%3};"
        : "+f"(d[0]), "+f"(d[1]), "+f"(d[2]), "+f"(d[3])
        : "r"(a[0]), "r"(a[1]), "r"(a[2]), "r"(a[3]), "r"(b0), "r"(b1));
}

__device__ __forceinline__ void ldsm4(uint32_t& r0, uint32_t& r1,
                                      uint32_t& r2, uint32_t& r3, uint32_t addr) {
    asm volatile("ldmatrix.sync.aligned.m8n8.x4.shared.b16 {%0,%1,%2,%3}, [%4];"
                 : "=r"(r0), "=r"(r1), "=r"(r2), "=r"(r3) : "r"(addr));
}

__device__ __forceinline__ uint32_t pack_bf16(float x, float y) {
    __nv_bfloat162 t(__float2bfloat16(x), __float2bfloat16(y));
    return *(uint32_t*)&t;
}

// ---------------- fp32 -> bf16 hi/lo split (one-time, streaming) ----------
__global__ void __launch_bounds__(256) k_splitg(const float* __restrict__ in,
                                                int which)
{
    __nv_bfloat16 *hi, *lo;
    if      (which == 0) { hi = g_xh;  lo = g_xl;  }
    else if (which == 1) { hi = g_wqh; lo = g_wql; }
    else if (which == 2) { hi = g_woh; lo = g_wol; }
    else                 { hi = g_aoh; lo = g_aol; in = g_ao; }

    int i = (blockIdx.x * 256 + threadIdx.x) * 4;
    float4 v = *(const float4*)(in + i);
    __nv_bfloat16 h0 = __float2bfloat16(v.x);
    __nv_bfloat16 h1 = __float2bfloat16(v.y);
    __nv_bfloat16 h2 = __float2bfloat16(v.z);
    __nv_bfloat16 h3 = __float2bfloat16(v.w);
    *(__nv_bfloat162*)(hi + i)     = __nv_bfloat162(h0, h1);
    *(__nv_bfloat162*)(hi + i + 2) = __nv_bfloat162(h2, h3);
    *(__nv_bfloat162*)(lo + i)     = __nv_bfloat162(
        __float2bfloat16(v.x - __bfloat162float(h0)),
        __float2bfloat16(v.y - __bfloat162float(h1)));
    *(__nv_bfloat162*)(lo + i + 2) = __nv_bfloat162(
        __float2bfloat16(v.z - __bfloat162float(h2)),
        __float2bfloat16(v.w - __bfloat162float(h3)));
}

// ---------------- HMMA split-bf16 GEMM (warp tile 64x64, CTA 128x256) ------
// C[M,N] = Ahi.Bhi^T + Ahi.Blo^T + Alo.Bhi^T ; operands [.,1024] K-major bf16.
// CTA tile 128x256, BK=32, 256 threads = 8 warps (2x4), warp tile 64x64.
#define LDAH  40                 // smem row stride in halves (80 B)
#define SM_AH 0
#define SM_AL (128 * LDAH)
#define SM_BH (2 * 128 * LDAH)
#define SM_BL (2 * 128 * LDAH + 256 * LDAH)
#define GEMM_SMEM_B ((2 * 128 + 2 * 256) * LDAH * 2)   // 61440 B

__device__ __forceinline__ void gemm_pre(const __nv_bfloat16* __restrict__ Ahi,
                                         const __nv_bfloat16* __restrict__ Alo,
                                         const __nv_bfloat16* __restrict__ Bhi,
                                         const __nv_bfloat16* __restrict__ Blo,
                                         float* __restrict__ C, int N)
{
    extern __shared__ __align__(16) __nv_bfloat16 sm[];
    __nv_bfloat16* Ah = sm + SM_AH;
    __nv_bfloat16* Al = sm + SM_AL;
    __nv_bfloat16* Bh = sm + SM_BH;
    __nv_bfloat16* Bl = sm + SM_BL;

    const int tid  = threadIdx.x;
    const int lane = tid & 31;
    const int wid  = tid >> 5;
    const int wm   = wid & 1;                // 0..1 -> 64-row slice
    const int wn   = wid >> 1;               // 0..3 -> 64-col slice
    const int gid  = lane >> 2;
    const int tig  = lane & 3;
    const int bm   = blockIdx.y * 128;
    const int bn   = blockIdx.x * 256;

    // ldmatrix lane roles
    const int lr   = lane & 7;
    const int qd   = lane >> 3;              // quadrant 0..3
    const int arow = (qd & 1) * 8 + lr;      // A atom quadrants
    const int acol = (qd >> 1) * 8;
    const int brow = (qd >> 1) * 8 + lr;     // B pair quadrants
    const int bcol = (qd & 1) * 8;

    const uint32_t ah_b = smem_u32(Ah);
    const uint32_t al_b = smem_u32(Al);
    const uint32_t bh_b = smem_u32(Bh);
    const uint32_t bl_b = smem_u32(Bl);

    // A load mapping: 128 rows x 4 segs, 2 threads/row
    const int rowA = tid >> 1;               // 0..127
    const int sgA  = (tid & 1) * 2;          // segs {0,1} or {2,3}

    float acc[4][8][4];
#pragma unroll
    for (int i = 0; i < 4; i++)
#pragma unroll
        for (int j = 0; j < 8; j++)
#pragma unroll
            for (int k = 0; k < 4; k++) acc[i][j][k] = 0.0f;

    uint4 pah[2], pal[2], pbh[4], pbl[4];

    auto fetch = [&](int kk) {
#pragma unroll
        for (int i = 0; i < 2; i++) {
            const int ke = kk + (sgA + i) * 8;
            pah[i] = *(const uint4*)(Ahi + (size_t)(bm + rowA) * DM_ + ke);
            pal[i] = *(const uint4*)(Alo + (size_t)(bm + rowA) * DM_ + ke);
        }
#pragma unroll
        for (int i = 0; i < 4; i++) {
            const int idx = i * 256 + tid;   // 0..1023
            const int rb  = idx >> 2;        // 0..255
            const int ke  = kk + (idx & 3) * 8;
            pbh[i] = *(const uint4*)(Bhi + (size_t)(bn + rb) * DM_ + ke);
            pbl[i] = *(const uint4*)(Blo + (size_t)(bn + rb) * DM_ + ke);
        }
    };

    fetch(0);

    const int NC = DM_ / 32;               // 32 chunks
    for (int c = 0; c < NC; c++) {
#pragma unroll
        for (int i = 0; i < 2; i++) {
            const int sc = (sgA + i) * 8;
            *(uint4*)&Ah[rowA * LDAH + sc] = pah[i];
            *(uint4*)&Al[rowA * LDAH + sc] = pal[i];
        }
#pragma unroll
        for (int i = 0; i < 4; i++) {
            const int idx = i * 256 + tid;
            const int rb  = idx >> 2;
            const int sc  = (idx & 3) * 8;
            *(uint4*)&Bh[rb * LDAH + sc] = pbh[i];
            *(uint4*)&Bl[rb * LDAH + sc] = pbl[i];
        }
        __syncthreads();

        if (c + 1 < NC) fetch((c + 1) * 32);   // LDGs ride out during MMAs

#pragma unroll
        for (int ks = 0; ks < 2; ks++) {
            uint32_t ah[4][4], al[4][4];
#pragma unroll
            for (int mi = 0; mi < 4; mi++) {
                const uint32_t off =
                    (uint32_t)((wm * 64 + mi * 16 + arow) * LDAH + ks * 16 + acol) * 2;
                ldsm4(ah[mi][0], ah[mi][1], ah[mi][2], ah[mi][3], ah_b + off);
                ldsm4(al[mi][0], al[mi][1], al[mi][2], al[mi][3], al_b + off);
            }
#pragma unroll
            for (int pg = 0; pg < 4; pg++) {
                const uint32_t off =
                    (uint32_t)((wn * 64 + pg * 16 + brow) * LDAH + ks * 16 + bcol) * 2;
                uint32_t bh0, bh1, bh2, bh3, bl0, bl1, bl2, bl3;
                ldsm4(bh0, bh1, bh2, bh3, bh_b + off);
                ldsm4(bl0, bl1, bl2, bl3, bl_b + off);
                const int n0 = pg * 2, n1 = pg * 2 + 1;
#pragma unroll
                for (int mi = 0; mi < 4; mi++) {
                    mma16816(acc[mi][n0], ah[mi], bh0, bh1);
                    mma16816(acc[mi][n0], ah[mi], bl0, bl1);
                    mma16816(acc[mi][n0], al[mi], bh0, bh1);
                    mma16816(acc[mi][n1], ah[mi], bh2, bh3);
                    mma16816(acc[mi][n1], ah[mi], bl2, bl3);
                    mma16816(acc[mi][n1], al[mi], bh2, bh3);
                }
            }
        }
        __syncthreads();
    }

#pragma unroll
    for (int mi = 0; mi < 4; mi++) {
        const int r = bm + wm * 64 + mi * 16 + gid;
#pragma unroll
        for (int ng = 0; ng < 8; ng++) {
            const int col = bn + wn * 64 + ng * 8 + tig * 2;
            *(float2*)&C[(size_t)r * N + col] =
                make_float2(acc[mi][ng][0], acc[mi][ng][1]);
            *(float2*)&C[(size_t)(r + 8) * N + col] =
                make_float2(acc[mi][ng][2], acc[mi][ng][3]);
        }
    }
}

__global__ void __launch_bounds__(256, 1) k_gemm_qkv()
{
    gemm_pre(g_xh, g_xl, g_wqh, g_wql, g_qkv, 3 * DM_);
}

__global__ void __launch_bounds__(256, 1) k_gemm_out(float* __restrict__ out)
{
    gemm_pre(g_aoh, g_aol, g_woh, g_wol, out, DM_);
}

// ---------------- RoPE + bf16 hi/lo split + head layout + V transpose ------
__global__ void __launch_bounds__(256) k_rope(const int* __restrict__ tp)
{
    int idx = blockIdx.x * 256 + threadIdx.x;
    int i = idx & 31;
    int s = (idx >> 5) & (S_ - 1);
    int h = (idx >> 16) & (H_ - 1);
    int b = idx >> 20;

    const int m = b * S_ + s;
    const float* base = g_qkv + (size_t)m * (3 * DM_) + h * DH_;

    float pos = (float)tp[s];
    float inv = powf(10000.0f, -(float)i * (1.0f / 32.0f));
    float ang = pos * inv;
    float sn, cs;
    sincosf(ang, &sn, &cs);

    float qe = base[2 * i],            qo = base[2 * i + 1];
    float ke = base[DM_ + 2 * i],      ko = base[DM_ + 2 * i + 1];
    float ve = base[2 * DM_ + 2 * i],  vo = base[2 * DM_ + 2 * i + 1];

    float rqe = (qe * cs - qo * sn) * 0.125f;
    float rqo = (qo * cs + qe * sn) * 0.125f;
    float rke = ke * cs - ko * sn;
    float rko = ko * cs + ke * sn;

    size_t o = ((size_t)(b * H_ + h) * S_ + s) * DH_ + 2 * i;

    __nv_bfloat16 qh0 = __float2bfloat16(rqe), qh1 = __float2bfloat16(rqo);
    __nv_bfloat16 kh0 = __float2bfloat16(rke), kh1 = __float2bfloat16(rko);
    *(__nv_bfloat162*)&g_qhi[o] = __nv_bfloat162(qh0, qh1);
    *(__nv_bfloat162*)&g_qlo[o] = __nv_bfloat162(
        __float2bfloat16(rqe - __bfloat162float(qh0)),
        __float2bfloat16(rqo - __bfloat162float(qh1)));
    *(__nv_bfloat162*)&g_khi[o] = __nv_bfloat162(kh0, kh1);
    *(__nv_bfloat162*)&g_klo[o] = __nv_bfloat162(
        __float2bfloat16(rke - __bfloat162float(kh0)),
        __float2bfloat16(rko - __bfloat162float(kh1)));

    // V transpose via smem: block = one (b,h), 8 consecutive s
    __shared__ __nv_bfloat16 svh[64][10], svl[64][10];
    const int sl = (threadIdx.x >> 5) & 7;
    __nv_bfloat16 vh0 = __float2bfloat16(ve), vh1 = __float2bfloat16(vo);
    svh[2 * i][sl]     = vh0;
    svh[2 * i + 1][sl] = vh1;
    svl[2 * i][sl]     = __float2bfloat16(ve - __bfloat162float(vh0));
    svl[2 * i + 1][sl] = __float2bfloat16(vo - __bfloat162float(vh1));
    __syncthreads();

    if (threadIdx.x < 128) {
        const int s0  = (blockIdx.x * 8) & (S_ - 1);
        const int idx0 = blockIdx.x * 256;
        const int h0  = (idx0 >> 16) & (H_ - 1);
        const int b0  = idx0 >> 20;
        const int bh  = b0 * H_ + h0;
        const int d   = threadIdx.x >> 1;
        const int sg  = (threadIdx.x & 1) * 4;

        unsigned short uh[4], ul[4];
#pragma unroll
        for (int j = 0; j < 4; j++) {
            uh[j] = *(unsigned short*)&svh[d][sg + j];
            ul[j] = *(unsigned short*)&svl[d][sg + j];
        }
        size_t vo_ = ((size_t)bh * DH_ + d) * S_ + s0 + sg;
        *(uint2*)&g_vthi[vo_] = *(uint2*)uh;
        *(uint2*)&g_vtlo[vo_] = *(uint2*)ul;
    }
}

// ---------------- HMMA flash attention (split-bf16, causal, ldmatrix) ------
// grid (S/64, B*H), 128 threads = 4 warps; warp = 16 q-rows, key tiles of 64.
#define LDK 72     // 144 B stride: 8 distinct 16B phases -> conflict-free ldmatrix

__global__ void __launch_bounds__(128) k_attn_mma()
{
    const int bh  = blockIdx.y;
    const int q0  = blockIdx.x * 64;
    const int tid = threadIdx.x;
    const int lane = tid & 31;
    const int w    = tid >> 5;
    const int gid  = lane >> 2;
    const int tig  = lane & 3;

    // ldmatrix lane roles (same derivation as GEMM)
    const int lr   = lane & 7;
    const int qd   = lane >> 3;
    const int arow = (qd & 1) * 8 + lr;
    const int acol = (qd >> 1) * 8;
    const int brow = (qd >> 1) * 8 + lr;
    const int bcol = (qd & 1) * 8;

    __shared__ __align__(16) __nv_bfloat16 Khi[64][LDK], Klo[64][LDK];
    __shared__ __align__(16) __nv_bfloat16 Vth[64][LDK], Vtl[64][LDK];

    const uint32_t kh_b = smem_u32(&Khi[0][0]);
    const uint32_t kl_b = smem_u32(&Klo[0][0]);
    const uint32_t vh_b = smem_u32(&Vth[0][0]);
    const uint32_t vl_b = smem_u32(&Vtl[0][0]);

    const __nv_bfloat16* qhi = g_qhi + (size_t)bh * S_ * DH_;
    const __nv_bfloat16* qlo = g_qlo + (size_t)bh * S_ * DH_;
    const __nv_bfloat16* khi = g_khi + (size_t)bh * S_ * DH_;
    const __nv_bfloat16* klo = g_klo + (size_t)bh * S_ * DH_;
    const __nv_bfloat16* vth = g_vthi + (size_t)bh * DH_ * S_;
    const __nv_bfloat16* vtl = g_vtlo + (size_t)bh * DH_ * S_;

    const int row0 = tid >> 1;            // 0..63
    const int seg0 = (tid & 1) * 4;       // 16B segs {0..3} or {4..7}

    // ---- stage Q tile (reuse K smem), extract fragments via ldmatrix ----
#pragma unroll
    for (int i2 = 0; i2 < 4; i2++) {
        *(uint4*)&Khi[row0][(seg0 + i2) * 8] =
            *(const uint4*)(qhi + (size_t)(q0 + row0) * DH_ + (seg0 + i2) * 8);
        *(uint4*)&Klo[row0][(seg0 + i2) * 8] =
            *(const uint4*)(qlo + (size_t)(q0 + row0) * DH_ + (seg0 + i2) * 8);
    }
    __syncthreads();

    uint32_t qh[4][4], ql[4][4];
#pragma unroll
    for (int kb = 0; kb < 4; kb++) {
        const uint32_t off =
            (uint32_t)((w * 16 + arow) * LDK + kb * 16 + acol) * 2;
        ldsm4(qh[kb][0], qh[kb][1], qh[kb][2], qh[kb][3], kh_b + off);
        ldsm4(ql[kb][0], ql[kb][1], ql[kb][2], ql[kb][3], kl_b + off);
    }
    __syncthreads();

    float o[8][4];
#pragma unroll
    for (int j = 0; j < 8; j++)
#pragma unroll
        for (int c = 0; c < 4; c++) o[j][c] = 0.0f;
    float m0 = -INFINITY, m1 = -INFINITY, l0 = 0.0f, l1 = 0.0f;

    const int r0a = q0 + w * 16 + gid;

    for (int kt = 0; kt <= q0; kt += 64) {
#pragma unroll
        for (int i2 = 0; i2 < 4; i2++) {
            const int sg = (seg0 + i2) * 8;
            *(uint4*)&Khi[row0][sg] =
                *(const uint4*)(khi + (size_t)(kt + row0) * DH_ + sg);
            *(uint4*)&Klo[row0][sg] =
                *(const uint4*)(klo + (size_t)(kt + row0) * DH_ + sg);
            *(uint4*)&Vth[row0][sg] =
                *(const uint4*)(vth + (size_t)row0 * S_ + kt + sg);
            *(uint4*)&Vtl[row0][sg] =
                *(const uint4*)(vtl + (size_t)row0 * S_ + kt + sg);
        }
        __syncthreads();

        // ---- scores: S = Qhi.Khi + Qhi.Klo + Qlo.Khi ----
        float s[8][4];
#pragma unroll
        for (int j = 0; j < 8; j++)
#pragma unroll
            for (int c = 0; c < 4; c++) s[j][c] = 0.0f;

#pragma unroll
        for (int kb = 0; kb < 4; kb++) {
#pragma unroll
            for (int jp = 0; jp < 4; jp++) {
                const uint32_t off =
                    (uint32_t)((jp * 16 + brow) * LDK + kb * 16 + bcol) * 2;
                uint32_t kh0, kh1, kh2, kh3, kl0, kl1, kl2, kl3;
                ldsm4(kh0, kh1, kh2, kh3, kh_b + off);
                ldsm4(kl0, kl1, kl2, kl3, kl_b + off);
                const int j0 = jp * 2, j1 = jp * 2 + 1;
                mma16816(s[j0], qh[kb], kh0, kh1);
                mma16816(s[j0], qh[kb], kl0, kl1);
                mma16816(s[j0], ql[kb], kh0, kh1);
                mma16816(s[j1], qh[kb], kh2, kh3);
                mma16816(s[j1], qh[kb], kl2, kl3);
                mma16816(s[j1], ql[kb], kh2, kh3);
            }
        }

        // ---- causal mask (diagonal block only) ----
        if (kt == q0) {
#pragma unroll
            for (int j = 0; j < 8; j++) {
                const int cb = kt + j * 8 + 2 * tig;
                if (cb     > r0a)     s[j][0] = -INFINITY;
                if (cb + 1 > r0a)     s[j][1] = -INFINITY;
                if (cb     > r0a + 8) s[j][2] = -INFINITY;
                if (cb + 1 > r0a + 8) s[j][3] = -INFINITY;
            }
        }

        // ---- online softmax ----
        float tm0 = m0, tm1 = m1;
#pragma unroll
        for (int j = 0; j < 8; j++) {
            tm0 = fmaxf(tm0, fmaxf(s[j][0], s[j][1]));
            tm1 = fmaxf(tm1, fmaxf(s[j][2], s[j][3]));
        }
        tm0 = fmaxf(tm0, __shfl_xor_sync(0xffffffff, tm0, 1));
        tm0 = fmaxf(tm0, __shfl_xor_sync(0xffffffff, tm0, 2));
        tm1 = fmaxf(tm1, __shfl_xor_sync(0xffffffff, tm1, 1));
        tm1 = fmaxf(tm1, __shfl_xor_sync(0xffffffff, tm1, 2));

        const float sc0 = __expf(m0 - tm0);
        const float sc1 = __expf(m1 - tm1);
        m0 = tm0; m1 = tm1;
        l0 *= sc0; l1 *= sc1;
#pragma unroll
        for (int j = 0; j < 8; j++) {
            o[j][0] *= sc0; o[j][1] *= sc0;
            o[j][2] *= sc1; o[j][3] *= sc1;
        }

        float rs0 = 0.0f, rs1 = 0.0f;
#pragma unroll
        for (int j = 0; j < 8; j++) {
            s[j][0] = __expf(s[j][0] - m0);
            s[j][1] = __expf(s[j][1] - m0);
            s[j][2] = __expf(s[j][2] - m1);
            s[j][3] = __expf(s[j][3] - m1);
            rs0 += s[j][0] + s[j][1];
            rs1 += s[j][2] + s[j][3];
        }
        rs0 += __shfl_xor_sync(0xffffffff, rs0, 1);
        rs0 += __shfl_xor_sync(0xffffffff, rs0, 2);
        rs1 += __shfl_xor_sync(0xffffffff, rs1, 1);
        rs1 += __shfl_xor_sync(0xffffffff, rs1, 2);
        l0 += rs0; l1 += rs1;

        // ---- P into A-fragments (hi/lo) ----
        uint32_t ph[4][4], pl[4][4];
#pragma unroll
        for (int kb = 0; kb < 4; kb++) {
            const int j0 = 2 * kb, j1 = 2 * kb + 1;
            ph[kb][0] = pack_bf16(s[j0][0], s[j0][1]);
            ph[kb][1] = pack_bf16(s[j0][2], s[j0][3]);
            ph[kb][2] = pack_bf16(s[j1][0], s[j1][1]);
            ph[kb][3] = pack_bf16(s[j1][2], s[j1][3]);
            __nv_bfloat162 h0 = *(__nv_bfloat162*)&ph[kb][0];
            __nv_bfloat162 h1 = *(__nv_bfloat162*)&ph[kb][1];
            __nv_bfloat162 h2 = *(__nv_bfloat162*)&ph[kb][2];
            __nv_bfloat162 h3 = *(__nv_bfloat162*)&ph[kb][3];
            pl[kb][0] = pack_bf16(s[j0][0] - __bfloat162float(h0.x),
                                  s[j0][1] - __bfloat162float(h0.y));
            pl[kb][1] = pack_bf16(s[j0][2] - __bfloat162float(h1.x),
                                  s[j0][3] - __bfloat162float(h1.y));
            pl[kb][2] = pack_bf16(s[j1][0] - __bfloat162float(h2.x),
                                  s[j1][1] - __bfloat162float(h2.y));
            pl[kb][3] = pack_bf16(s[j1][2] - __bfloat162float(h3.x),
                                  s[j1][3] - __bfloat162float(h3.y));
        }

        // ---- O += P.V : Phi.Vhi + Phi.Vlo + Plo.Vhi ----
#pragma unroll
        for (int kb = 0; kb < 4; kb++) {
#pragma unroll
            for (int jp = 0; jp < 4; jp++) {
                const uint32_t off =
                    (uint32_t)((jp * 16 + brow) * LDK + kb * 16 + bcol) * 2;
                uint32_t vh0, vh1, vh2, vh3, vl0, vl1, vl2, vl3;
                ldsm4(vh0, vh1, vh2, vh3, vh_b + off);
                ldsm4(vl0, vl1, vl2, vl3, vl_b + off);
                const int j0 = jp * 2, j1 = jp * 2 + 1;
                mma16816(o[j0], ph[kb], vh0, vh1);
                mma16816(o[j0], ph[kb], vl0, vl1);
                mma16816(o[j0], pl[kb], vh0, vh1);
                mma16816(o[j1], ph[kb], vh2, vh3);
                mma16816(o[j1], ph[kb], vl2, vl3);
                mma16816(o[j1], pl[kb], vh2, vh3);
            }
        }
        __syncthreads();
    }

    // ---- epilogue ----
    const float inv0 = 1.0f / l0;
    const float inv1 = 1.0f / l1;
    const int b = bh >> 4, h = bh & 15;
#pragma unroll
    for (int j = 0; j < 8; j++) {
        const int col = h * DH_ + j * 8 + 2 * tig;
        *(float2*)&g_ao[(size_t)(b * S_ + r0a) * DM_ + col] =
            make_float2(o[j][0] * inv0, o[j][1] * inv0);
        *(float2*)&g_ao[(size_t)(b * S_ + r0a + 8) * DM_ + col] =
            make_float2(o[j][2] * inv1, o[j][3] * inv1);
    }
}

// ---------------- launch ----------------
extern "C" void kernel_launch(void* const* d_in, const int* in_sizes, int n_in,
                              void* d_out, int out_size)
{
    const float* x      = (const float*)d_in[0];
    const float* w_qkv  = (const float*)d_in[1];
    const float* w_o    = (const float*)d_in[2];
    const int*   tp     = (const int*)d_in[3];

    static bool attr_done = false;
    if (!attr_done) {
        cudaFuncSetAttribute(k_gemm_qkv,
            cudaFuncAttributeMaxDynamicSharedMemorySize, GEMM_SMEM_B);
        cudaFuncSetAttribute(k_gemm_out,
            cudaFuncAttributeMaxDynamicSharedMemorySize, GEMM_SMEM_B);
        attr_done = true;
    }

    // 0) one-time bf16 hi/lo splits of x, w_qkv, w_o
    k_splitg<<<(MTOK * DM_) / 1024, 256>>>(x, 0);
    k_splitg<<<(3 * DM_ * DM_) / 1024, 256>>>(w_qkv, 1);
    k_splitg<<<(DM_ * DM_) / 1024, 256>>>(w_o, 2);

    // 1) QKV projection (HMMA, warp tile 64x64)
    k_gemm_qkv<<<dim3(3 * DM_ / 256, MTOK / 128), 256, GEMM_SMEM_B>>>();

    // 2) RoPE + bf16 hi/lo per-head layout + V transpose
    k_rope<<<(B_ * H_ * S_ * 32) / 256, 256>>>(tp);

    // 3) causal flash attention (HMMA + ldmatrix)
    k_attn_mma<<<dim3(S_ / 64, B_ * H_), 128>>>();

    // 4) split attention output, output projection
    k_splitg<<<(MTOK * DM_) / 1024, 256>>>(nullptr, 3);
    k_gemm_out<<<dim3(DM_ / 256, MTOK / 128), 256, GEMM_SMEM_B>>>((float*)d_out);
}

// round 12
// speedup vs baseline: 1.7586x; 1.0985x over previous
#include <cuda_runtime.h>
#include <cuda_bf16.h>
#include <cstdint>
#include <math.h>

#define B_   2
#define S_   2048
#define H_   16
#define DH_  64
#define DM_  1024
#define MTOK (B_ * S_)        // 4096

// ---------------- scratch (device-code references ONLY) ----------------
__device__ float g_qkv[(size_t)MTOK * 3 * DM_];     // 48 MB
__device__ float g_ao [(size_t)MTOK * DM_];         // 16 MB
__device__ float2 g_rope_tab[S_ * 32];              // cos/sin per (s, i)

// bf16 hi/lo GEMM operands
__device__ __nv_bfloat16 g_xh [(size_t)MTOK * DM_];
__device__ __nv_bfloat16 g_xl [(size_t)MTOK * DM_];
__device__ __nv_bfloat16 g_wqh[(size_t)3 * DM_ * DM_];
__device__ __nv_bfloat16 g_wql[(size_t)3 * DM_ * DM_];
__device__ __nv_bfloat16 g_woh[(size_t)DM_ * DM_];
__device__ __nv_bfloat16 g_wol[(size_t)DM_ * DM_];
__device__ __nv_bfloat16 g_aoh[(size_t)MTOK * DM_];
__device__ __nv_bfloat16 g_aol[(size_t)MTOK * DM_];

// bf16 hi/lo attention operands (Q has 0.125 score scale folded in)
__device__ __nv_bfloat16 g_qhi[(size_t)B_ * H_ * S_ * DH_];
__device__ __nv_bfloat16 g_qlo[(size_t)B_ * H_ * S_ * DH_];
__device__ __nv_bfloat16 g_khi[(size_t)B_ * H_ * S_ * DH_];
__device__ __nv_bfloat16 g_klo[(size_t)B_ * H_ * S_ * DH_];
__device__ __nv_bfloat16 g_vthi[(size_t)B_ * H_ * DH_ * S_];  // transposed [bh][d][s]
__device__ __nv_bfloat16 g_vtlo[(size_t)B_ * H_ * DH_ * S_];

// ---------------- helpers ----------------
__device__ __forceinline__ uint32_t smem_u32(const void* p) {
    uint32_t a;
    asm("{ .reg .u64 t; cvta.to.shared.u64 t, %1; cvt.u32.u64 %0, t; }"
        : "=r"(a) : "l"(p));
    return a;
}

__device__ __forceinline__ void mma16816(float* d, const uint32_t* a,
                                         uint32_t b0, uint32_t b1) {
    asm volatile(
        "mma.sync.aligned.m16n8k16.row.col.f32.bf16.bf16.f32 "
        "{%0,%1,%2,%3}, {%4,%5,%6,%7}, {%8,%9}, {%0,%1,%2,%3};"
        : "+f"(d[0]), "+f"(d[1]), "+f"(d[2]), "+f"(d[3])
        : "r"(a[0]), "r"(a[1]), "r"(a[2]), "r"(a[3]), "r"(b0), "r"(b1));
}

__device__ __forceinline__ void ldsm4(uint32_t& r0, uint32_t& r1,
                                      uint32_t& r2, uint32_t& r3, uint32_t addr) {
    asm volatile("ldmatrix.sync.aligned.m8n8.x4.shared.b16 {%0,%1,%2,%3}, [%4];"
                 : "=r"(r0), "=r"(r1), "=r"(r2), "=r"(r3) : "r"(addr));
}

__device__ __forceinline__ uint32_t pack_bf16(float x, float y) {
    __nv_bfloat162 t(__float2bfloat16(x), __float2bfloat16(y));
    return *(uint32_t*)&t;
}

// ---------------- fp32 -> bf16 hi/lo split (one-time, streaming) ----------
__global__ void __launch_bounds__(256) k_splitg(const float* __restrict__ in,
                                                int which)
{
    __nv_bfloat16 *hi, *lo;
    if      (which == 0) { hi = g_xh;  lo = g_xl;  }
    else if (which == 1) { hi = g_wqh; lo = g_wql; }
    else if (which == 2) { hi = g_woh; lo = g_wol; }
    else                 { hi = g_aoh; lo = g_aol; in = g_ao; }

    int i = (blockIdx.x * 256 + threadIdx.x) * 4;
    float4 v = *(const float4*)(in + i);
    __nv_bfloat16 h0 = __float2bfloat16(v.x);
    __nv_bfloat16 h1 = __float2bfloat16(v.y);
    __nv_bfloat16 h2 = __float2bfloat16(v.z);
    __nv_bfloat16 h3 = __float2bfloat16(v.w);
    *(__nv_bfloat162*)(hi + i)     = __nv_bfloat162(h0, h1);
    *(__nv_bfloat162*)(hi + i + 2) = __nv_bfloat162(h2, h3);
    *(__nv_bfloat162*)(lo + i)     = __nv_bfloat162(
        __float2bfloat16(v.x - __bfloat162float(h0)),
        __float2bfloat16(v.y - __bfloat162float(h1)));
    *(__nv_bfloat162*)(lo + i + 2) = __nv_bfloat162(
        __float2bfloat16(v.z - __bfloat162float(h2)),
        __float2bfloat16(v.w - __bfloat162float(h3)));
}

// ---------------- HMMA split-bf16 GEMM -------------------------------------
// CTA tile 128x256, BK=16, double-buffered smem, 8 warps (2x4), warp 64x64.
#define LDT 24                         // halves per smem row (48 B stride)
#define A_TILE_H (128 * LDT)           // 3072 halves
#define B_TILE_H (256 * LDT)           // 6144 halves
#define BUF_H    (2 * A_TILE_H + 2 * B_TILE_H)   // 18432 halves
#define GEMM_SMEM_B (2 * BUF_H * 2)    // 73728 bytes

__device__ __forceinline__ void gemm_pre(const __nv_bfloat16* __restrict__ Ahi,
                                         const __nv_bfloat16* __restrict__ Alo,
                                         const __nv_bfloat16* __restrict__ Bhi,
                                         const __nv_bfloat16* __restrict__ Blo,
                                         float* __restrict__ C, int N)
{
    extern __shared__ __align__(16) __nv_bfloat16 sm[];
    const uint32_t sm0 = smem_u32(sm);

    const int tid  = threadIdx.x;
    const int lane = tid & 31;
    const int wid  = tid >> 5;
    const int wm   = wid & 1;                // 0..1 -> 64-row slice
    const int wn   = wid >> 1;               // 0..3 -> 64-col slice
    const int gid  = lane >> 2;
    const int tig  = lane & 3;
    const int bm   = blockIdx.y * 128;
    const int bn   = blockIdx.x * 256;

    // ldmatrix lane roles
    const int lr   = lane & 7;
    const int qd   = lane >> 3;
    const int arow = (qd & 1) * 8 + lr;
    const int acol = (qd >> 1) * 8;
    const int brow = (qd >> 1) * 8 + lr;
    const int bcol = (qd & 1) * 8;

    // load mapping: 2 threads per row (segs 0/1 of 8 halves)
    const int rowA = tid >> 1;               // 0..127
    const int sgA  = tid & 1;

    float acc[4][8][4];
#pragma unroll
    for (int i = 0; i < 4; i++)
#pragma unroll
        for (int j = 0; j < 8; j++)
#pragma unroll
            for (int k = 0; k < 4; k++) acc[i][j][k] = 0.0f;

    uint4 pah, pal, pbh[2], pbl[2];

    auto fetch = [&](int c) {
        const int kk = c << 4;
        const int ke = kk + sgA * 8;
        pah = *(const uint4*)(Ahi + (size_t)(bm + rowA) * DM_ + ke);
        pal = *(const uint4*)(Alo + (size_t)(bm + rowA) * DM_ + ke);
#pragma unroll
        for (int i = 0; i < 2; i++) {
            const int idx = i * 256 + tid;   // 0..511
            const int rb  = idx >> 1;        // 0..255
            const int keb = kk + (idx & 1) * 8;
            pbh[i] = *(const uint4*)(Bhi + (size_t)(bn + rb) * DM_ + keb);
            pbl[i] = *(const uint4*)(Blo + (size_t)(bn + rb) * DM_ + keb);
        }
    };

    fetch(0);

    const int NC = DM_ / 16;               // 64 chunks
    for (int c = 0; c < NC; c++) {
        const int buf = c & 1;
        __nv_bfloat16* base = sm + buf * BUF_H;

        // stage into buf (other buffer than the one MMA(c-1) just read)
        *(uint4*)&base[rowA * LDT + sgA * 8] = pah;
        *(uint4*)&base[A_TILE_H + rowA * LDT + sgA * 8] = pal;
#pragma unroll
        for (int i = 0; i < 2; i++) {
            const int idx = i * 256 + tid;
            const int rb  = idx >> 1;
            const int sg  = (idx & 1) * 8;
            *(uint4*)&base[2 * A_TILE_H + rb * LDT + sg] = pbh[i];
            *(uint4*)&base[2 * A_TILE_H + B_TILE_H + rb * LDT + sg] = pbl[i];
        }
        __syncthreads();

        if (c + 1 < NC) fetch(c + 1);      // LDGs ride out during MMAs

        const uint32_t bufb = sm0 + (uint32_t)buf * BUF_H * 2;

        uint32_t ah[4][4], al[4][4];
#pragma unroll
        for (int mi = 0; mi < 4; mi++) {
            const uint32_t aoff =
                (uint32_t)((wm * 64 + mi * 16 + arow) * LDT + acol) * 2;
            ldsm4(ah[mi][0], ah[mi][1], ah[mi][2], ah[mi][3], bufb + aoff);
            ldsm4(al[mi][0], al[mi][1], al[mi][2], al[mi][3],
                  bufb + A_TILE_H * 2 + aoff);
        }
#pragma unroll
        for (int pg = 0; pg < 4; pg++) {
            const uint32_t boff =
                (uint32_t)((wn * 64 + pg * 16 + brow) * LDT + bcol) * 2;
            uint32_t bh0, bh1, bh2, bh3, bl0, bl1, bl2, bl3;
            ldsm4(bh0, bh1, bh2, bh3, bufb + 4 * A_TILE_H + boff);
            ldsm4(bl0, bl1, bl2, bl3, bufb + 4 * A_TILE_H + B_TILE_H * 2 + boff);
            const int n0 = pg * 2, n1 = pg * 2 + 1;
#pragma unroll
            for (int mi = 0; mi < 4; mi++) {
                mma16816(acc[mi][n0], ah[mi], bh0, bh1);
                mma16816(acc[mi][n0], ah[mi], bl0, bl1);
                mma16816(acc[mi][n0], al[mi], bh0, bh1);
                mma16816(acc[mi][n1], ah[mi], bh2, bh3);
                mma16816(acc[mi][n1], ah[mi], bl2, bl3);
                mma16816(acc[mi][n1], al[mi], bh2, bh3);
            }
        }
    }

#pragma unroll
    for (int mi = 0; mi < 4; mi++) {
        const int r = bm + wm * 64 + mi * 16 + gid;
#pragma unroll
        for (int ng = 0; ng < 8; ng++) {
            const int col = bn + wn * 64 + ng * 8 + tig * 2;
            *(float2*)&C[(size_t)r * N + col] =
                make_float2(acc[mi][ng][0], acc[mi][ng][1]);
            *(float2*)&C[(size_t)(r + 8) * N + col] =
                make_float2(acc[mi][ng][2], acc[mi][ng][3]);
        }
    }
}

__global__ void __launch_bounds__(256, 1) k_gemm_qkv()
{
    gemm_pre(g_xh, g_xl, g_wqh, g_wql, g_qkv, 3 * DM_);
}

__global__ void __launch_bounds__(256, 1) k_gemm_out(float* __restrict__ out)
{
    gemm_pre(g_aoh, g_aol, g_woh, g_wol, out, DM_);
}

// ---------------- RoPE table (one-time; exact powf/sincosf) ----------------
__global__ void __launch_bounds__(256) k_ropetab(const int* __restrict__ tp)
{
    int idx = blockIdx.x * 256 + threadIdx.x;   // < 65536
    int s = idx >> 5, i = idx & 31;
    float pos = (float)tp[s];
    float inv = powf(10000.0f, -(float)i * (1.0f / 32.0f));
    float sn, cs;
    sincosf(pos * inv, &sn, &cs);
    g_rope_tab[idx] = make_float2(cs, sn);
}

// ---------------- RoPE + bf16 hi/lo split + head layout + V transpose ------
__global__ void __launch_bounds__(256) k_rope()
{
    int idx = blockIdx.x * 256 + threadIdx.x;
    int i = idx & 31;
    int s = (idx >> 5) & (S_ - 1);
    int h = (idx >> 16) & (H_ - 1);
    int b = idx >> 20;

    const int m = b * S_ + s;
    const float* base = g_qkv + (size_t)m * (3 * DM_) + h * DH_;

    float2 cs2 = g_rope_tab[idx & (S_ * 32 - 1)];
    const float cs = cs2.x, sn = cs2.y;

    float qe = base[2 * i],            qo = base[2 * i + 1];
    float ke = base[DM_ + 2 * i],      ko = base[DM_ + 2 * i + 1];
    float ve = base[2 * DM_ + 2 * i],  vo = base[2 * DM_ + 2 * i + 1];

    float rqe = (qe * cs - qo * sn) * 0.125f;
    float rqo = (qo * cs + qe * sn) * 0.125f;
    float rke = ke * cs - ko * sn;
    float rko = ko * cs + ke * sn;

    size_t o = ((size_t)(b * H_ + h) * S_ + s) * DH_ + 2 * i;

    __nv_bfloat16 qh0 = __float2bfloat16(rqe), qh1 = __float2bfloat16(rqo);
    __nv_bfloat16 kh0 = __float2bfloat16(rke), kh1 = __float2bfloat16(rko);
    *(__nv_bfloat162*)&g_qhi[o] = __nv_bfloat162(qh0, qh1);
    *(__nv_bfloat162*)&g_qlo[o] = __nv_bfloat162(
        __float2bfloat16(rqe - __bfloat162float(qh0)),
        __float2bfloat16(rqo - __bfloat162float(qh1)));
    *(__nv_bfloat162*)&g_khi[o] = __nv_bfloat162(kh0, kh1);
    *(__nv_bfloat162*)&g_klo[o] = __nv_bfloat162(
        __float2bfloat16(rke - __bfloat162float(kh0)),
        __float2bfloat16(rko - __bfloat162float(kh1)));

    // V transpose via smem: block = one (b,h), 8 consecutive s
    __shared__ __nv_bfloat16 svh[64][10], svl[64][10];
    const int sl = (threadIdx.x >> 5) & 7;
    __nv_bfloat16 vh0 = __float2bfloat16(ve), vh1 = __float2bfloat16(vo);
    svh[2 * i][sl]     = vh0;
    svh[2 * i + 1][sl] = vh1;
    svl[2 * i][sl]     = __float2bfloat16(ve - __bfloat162float(vh0));
    svl[2 * i + 1][sl] = __float2bfloat16(vo - __bfloat162float(vh1));
    __syncthreads();

    if (threadIdx.x < 128) {
        const int s0  = (blockIdx.x * 8) & (S_ - 1);
        const int idx0 = blockIdx.x * 256;
        const int h0  = (idx0 >> 16) & (H_ - 1);
        const int b0  = idx0 >> 20;
        const int bh  = b0 * H_ + h0;
        const int d   = threadIdx.x >> 1;
        const int sg  = (threadIdx.x & 1) * 4;

        unsigned short uh[4], ul[4];
#pragma unroll
        for (int j = 0; j < 4; j++) {
            uh[j] = *(unsigned short*)&svh[d][sg + j];
            ul[j] = *(unsigned short*)&svl[d][sg + j];
        }
        size_t vo_ = ((size_t)bh * DH_ + d) * S_ + s0 + sg;
        *(uint2*)&g_vthi[vo_] = *(uint2*)uh;
        *(uint2*)&g_vtlo[vo_] = *(uint2*)ul;
    }
}

// ---------------- HMMA flash attention (split-bf16, causal, ldmatrix) ------
// grid (S/64, B*H), 128 threads = 4 warps; warp = 16 q-rows, key tiles of 64.
#define LDK 72     // 144 B stride: 8 distinct 16B phases -> conflict-free ldmatrix

__global__ void __launch_bounds__(128) k_attn_mma()
{
    const int bh  = blockIdx.y;
    const int q0  = blockIdx.x * 64;
    const int tid = threadIdx.x;
    const int lane = tid & 31;
    const int w    = tid >> 5;
    const int gid  = lane >> 2;
    const int tig  = lane & 3;

    const int lr   = lane & 7;
    const int qd   = lane >> 3;
    const int arow = (qd & 1) * 8 + lr;
    const int acol = (qd >> 1) * 8;
    const int brow = (qd >> 1) * 8 + lr;
    const int bcol = (qd & 1) * 8;

    __shared__ __align__(16) __nv_bfloat16 Khi[64][LDK], Klo[64][LDK];
    __shared__ __align__(16) __nv_bfloat16 Vth[64][LDK], Vtl[64][LDK];

    const uint32_t kh_b = smem_u32(&Khi[0][0]);
    const uint32_t kl_b = smem_u32(&Klo[0][0]);
    const uint32_t vh_b = smem_u32(&Vth[0][0]);
    const uint32_t vl_b = smem_u32(&Vtl[0][0]);

    const __nv_bfloat16* qhi = g_qhi + (size_t)bh * S_ * DH_;
    const __nv_bfloat16* qlo = g_qlo + (size_t)bh * S_ * DH_;
    const __nv_bfloat16* khi = g_khi + (size_t)bh * S_ * DH_;
    const __nv_bfloat16* klo = g_klo + (size_t)bh * S_ * DH_;
    const __nv_bfloat16* vth = g_vthi + (size_t)bh * DH_ * S_;
    const __nv_bfloat16* vtl = g_vtlo + (size_t)bh * DH_ * S_;

    const int row0 = tid >> 1;            // 0..63
    const int seg0 = (tid & 1) * 4;       // 16B segs {0..3} or {4..7}

    // ---- stage Q tile (reuse K smem), extract fragments via ldmatrix ----
#pragma unroll
    for (int i2 = 0; i2 < 4; i2++) {
        *(uint4*)&Khi[row0][(seg0 + i2) * 8] =
            *(const uint4*)(qhi + (size_t)(q0 + row0) * DH_ + (seg0 + i2) * 8);
        *(uint4*)&Klo[row0][(seg0 + i2) * 8] =
            *(const uint4*)(qlo + (size_t)(q0 + row0) * DH_ + (seg0 + i2) * 8);
    }
    __syncthreads();

    uint32_t qh[4][4], ql[4][4];
#pragma unroll
    for (int kb = 0; kb < 4; kb++) {
        const uint32_t off =
            (uint32_t)((w * 16 + arow) * LDK + kb * 16 + acol) * 2;
        ldsm4(qh[kb][0], qh[kb][1], qh[kb][2], qh[kb][3], kh_b + off);
        ldsm4(ql[kb][0], ql[kb][1], ql[kb][2], ql[kb][3], kl_b + off);
    }
    __syncthreads();

    float o[8][4];
#pragma unroll
    for (int j = 0; j < 8; j++)
#pragma unroll
        for (int c = 0; c < 4; c++) o[j][c] = 0.0f;
    float m0 = -INFINITY, m1 = -INFINITY, l0 = 0.0f, l1 = 0.0f;

    const int r0a = q0 + w * 16 + gid;

    for (int kt = 0; kt <= q0; kt += 64) {
#pragma unroll
        for (int i2 = 0; i2 < 4; i2++) {
            const int sg = (seg0 + i2) * 8;
            *(uint4*)&Khi[row0][sg] =
                *(const uint4*)(khi + (size_t)(kt + row0) * DH_ + sg);
            *(uint4*)&Klo[row0][sg] =
                *(const uint4*)(klo + (size_t)(kt + row0) * DH_ + sg);
            *(uint4*)&Vth[row0][sg] =
                *(const uint4*)(vth + (size_t)row0 * S_ + kt + sg);
            *(uint4*)&Vtl[row0][sg] =
                *(const uint4*)(vtl + (size_t)row0 * S_ + kt + sg);
        }
        __syncthreads();

        float s[8][4];
#pragma unroll
        for (int j = 0; j < 8; j++)
#pragma unroll
            for (int c = 0; c < 4; c++) s[j][c] = 0.0f;

#pragma unroll
        for (int kb = 0; kb < 4; kb++) {
#pragma unroll
            for (int jp = 0; jp < 4; jp++) {
                const uint32_t off =
                    (uint32_t)((jp * 16 + brow) * LDK + kb * 16 + bcol) * 2;
                uint32_t kh0, kh1, kh2, kh3, kl0, kl1, kl2, kl3;
                ldsm4(kh0, kh1, kh2, kh3, kh_b + off);
                ldsm4(kl0, kl1, kl2, kl3, kl_b + off);
                const int j0 = jp * 2, j1 = jp * 2 + 1;
                mma16816(s[j0], qh[kb], kh0, kh1);
                mma16816(s[j0], qh[kb], kl0, kl1);
                mma16816(s[j0], ql[kb], kh0, kh1);
                mma16816(s[j1], qh[kb], kh2, kh3);
                mma16816(s[j1], qh[kb], kl2, kl3);
                mma16816(s[j1], ql[kb], kh2, kh3);
            }
        }

        if (kt == q0) {
#pragma unroll
            for (int j = 0; j < 8; j++) {
                const int cb = kt + j * 8 + 2 * tig;
                if (cb     > r0a)     s[j][0] = -INFINITY;
                if (cb + 1 > r0a)     s[j][1] = -INFINITY;
                if (cb     > r0a + 8) s[j][2] = -INFINITY;
                if (cb + 1 > r0a + 8) s[j][3] = -INFINITY;
            }
        }

        float tm0 = m0, tm1 = m1;
#pragma unroll
        for (int j = 0; j < 8; j++) {
            tm0 = fmaxf(tm0, fmaxf(s[j][0], s[j][1]));
            tm1 = fmaxf(tm1, fmaxf(s[j][2], s[j][3]));
        }
        tm0 = fmaxf(tm0, __shfl_xor_sync(0xffffffff, tm0, 1));
        tm0 = fmaxf(tm0, __shfl_xor_sync(0xffffffff, tm0, 2));
        tm1 = fmaxf(tm1, __shfl_xor_sync(0xffffffff, tm1, 1));
        tm1 = fmaxf(tm1, __shfl_xor_sync(0xffffffff, tm1, 2));

        const float sc0 = __expf(m0 - tm0);
        const float sc1 = __expf(m1 - tm1);
        m0 = tm0; m1 = tm1;
        l0 *= sc0; l1 *= sc1;
#pragma unroll
        for (int j = 0; j < 8; j++) {
            o[j][0] *= sc0; o[j][1] *= sc0;
            o[j][2] *= sc1; o[j][3] *= sc1;
        }

        float rs0 = 0.0f, rs1 = 0.0f;
#pragma unroll
        for (int j = 0; j < 8; j++) {
            s[j][0] = __expf(s[j][0] - m0);
            s[j][1] = __expf(s[j][1] - m0);
            s[j][2] = __expf(s[j][2] - m1);
            s[j][3] = __expf(s[j][3] - m1);
            rs0 += s[j][0] + s[j][1];
            rs1 += s[j][2] + s[j][3];
        }
        rs0 += __shfl_xor_sync(0xffffffff, rs0, 1);
        rs0 += __shfl_xor_sync(0xffffffff, rs0, 2);
        rs1 += __shfl_xor_sync(0xffffffff, rs1, 1);
        rs1 += __shfl_xor_sync(0xffffffff, rs1, 2);
        l0 += rs0; l1 += rs1;

        uint32_t ph[4][4], pl[4][4];
#pragma unroll
        for (int kb = 0; kb < 4; kb++) {
            const int j0 = 2 * kb, j1 = 2 * kb + 1;
            ph[kb][0] = pack_bf16(s[j0][0], s[j0][1]);
            ph[kb][1] = pack_bf16(s[j0][2], s[j0][3]);
            ph[kb][2] = pack_bf16(s[j1][0], s[j1][1]);
            ph[kb][3] = pack_bf16(s[j1][2], s[j1][3]);
            __nv_bfloat162 h0 = *(__nv_bfloat162*)&ph[kb][0];
            __nv_bfloat162 h1 = *(__nv_bfloat162*)&ph[kb][1];
            __nv_bfloat162 h2 = *(__nv_bfloat162*)&ph[kb][2];
            __nv_bfloat162 h3 = *(__nv_bfloat162*)&ph[kb][3];
            pl[kb][0] = pack_bf16(s[j0][0] - __bfloat162float(h0.x),
                                  s[j0][1] - __bfloat162float(h0.y));
            pl[kb][1] = pack_bf16(s[j0][2] - __bfloat162float(h1.x),
                                  s[j0][3] - __bfloat162float(h1.y));
            pl[kb][2] = pack_bf16(s[j1][0] - __bfloat162float(h2.x),
                                  s[j1][1] - __bfloat162float(h2.y));
            pl[kb][3] = pack_bf16(s[j1][2] - __bfloat162float(h3.x),
                                  s[j1][3] - __bfloat162float(h3.y));
        }

#pragma unroll
        for (int kb = 0; kb < 4; kb++) {
#pragma unroll
            for (int jp = 0; jp < 4; jp++) {
                const uint32_t off =
                    (uint32_t)((jp * 16 + brow) * LDK + kb * 16 + bcol) * 2;
                uint32_t vh0, vh1, vh2, vh3, vl0, vl1, vl2, vl3;
                ldsm4(vh0, vh1, vh2, vh3, vh_b + off);
                ldsm4(vl0, vl1, vl2, vl3, vl_b + off);
                const int j0 = jp * 2, j1 = jp * 2 + 1;
                mma16816(o[j0], ph[kb], vh0, vh1);
                mma16816(o[j0], ph[kb], vl0, vl1);
                mma16816(o[j0], pl[kb], vh0, vh1);
                mma16816(o[j1], ph[kb], vh2, vh3);
                mma16816(o[j1], ph[kb], vl2, vl3);
                mma16816(o[j1], pl[kb], vh2, vh3);
            }
        }
        __syncthreads();
    }

    const float inv0 = 1.0f / l0;
    const float inv1 = 1.0f / l1;
    const int b = bh >> 4, h = bh & 15;
#pragma unroll
    for (int j = 0; j < 8; j++) {
        const int col = h * DH_ + j * 8 + 2 * tig;
        *(float2*)&g_ao[(size_t)(b * S_ + r0a) * DM_ + col] =
            make_float2(o[j][0] * inv0, o[j][1] * inv0);
        *(float2*)&g_ao[(size_t)(b * S_ + r0a + 8) * DM_ + col] =
            make_float2(o[j][2] * inv1, o[j][3] * inv1);
    }
}

// ---------------- launch ----------------
extern "C" void kernel_launch(void* const* d_in, const int* in_sizes, int n_in,
                              void* d_out, int out_size)
{
    const float* x      = (const float*)d_in[0];
    const float* w_qkv  = (const float*)d_in[1];
    const float* w_o    = (const float*)d_in[2];
    const int*   tp     = (const int*)d_in[3];

    static bool attr_done = false;
    if (!attr_done) {
        cudaFuncSetAttribute(k_gemm_qkv,
            cudaFuncAttributeMaxDynamicSharedMemorySize, GEMM_SMEM_B);
        cudaFuncSetAttribute(k_gemm_out,
            cudaFuncAttributeMaxDynamicSharedMemorySize, GEMM_SMEM_B);
        attr_done = true;
    }

    // 0) one-time bf16 hi/lo splits + rope table
    k_splitg<<<(MTOK * DM_) / 1024, 256>>>(x, 0);
    k_splitg<<<(3 * DM_ * DM_) / 1024, 256>>>(w_qkv, 1);
    k_splitg<<<(DM_ * DM_) / 1024, 256>>>(w_o, 2);
    k_ropetab<<<(S_ * 32) / 256, 256>>>(tp);

    // 1) QKV projection
    k_gemm_qkv<<<dim3(3 * DM_ / 256, MTOK / 128), 256, GEMM_SMEM_B>>>();

    // 2) RoPE + bf16 hi/lo per-head layout + V transpose
    k_rope<<<(B_ * H_ * S_ * 32) / 256, 256>>>();

    // 3) causal flash attention
    k_attn_mma<<<dim3(S_ / 64, B_ * H_), 128>>>();

    // 4) split attention output, output projection
    k_splitg<<<(MTOK * DM_) / 1024, 256>>>(nullptr, 3);
    k_gemm_out<<<dim3(DM_ / 256, MTOK / 128), 256, GEMM_SMEM_B>>>((float*)d_out);
}